// round 1
// baseline (speedup 1.0000x reference)
#include <cuda_runtime.h>

// Problem constants
#define BB 4
#define TT 2048
#define CC 64
#define HH 6
#define DD 64
#define TILE 64
#define PAD 65
#define NEG_BIG (-1e30f)

// Scratch (allocation-free rule: __device__ globals)
__device__ float g_q[(size_t)BB*HH*TT*DD];
__device__ float g_k[(size_t)BB*HH*TT*DD];
__device__ float g_v[(size_t)BB*HH*TT*DD];
__device__ float g_o[(size_t)BB*HH*TT*DD];

// ---------------------------------------------------------------------------
// Kernel 1: QKV projection. grid (T/64, B*H, 3), block (16,16)
// sel 0: q = x @ Wq[h], sel 1: k = y @ Wk[h], sel 2: v = y @ Wv[h]
// ---------------------------------------------------------------------------
__global__ void qkv_kernel(const float* __restrict__ x, const float* __restrict__ y,
                           const float* __restrict__ Wq, const float* __restrict__ Wk,
                           const float* __restrict__ Wv) {
    __shared__ float a_s[TILE][PAD];
    __shared__ float w_s[TILE][PAD];

    const int sel = blockIdx.z;
    const int bh  = blockIdx.y;
    const int b   = bh / HH, h = bh % HH;
    const int t0  = blockIdx.x * TILE;

    const float* src = (sel == 0 ? x : y) + ((size_t)b * TT + t0) * CC;
    const float* W   = (sel == 0 ? Wq : (sel == 1 ? Wk : Wv)) + (size_t)h * CC * DD;
    float* out = (sel == 0 ? g_q : (sel == 1 ? g_k : g_v)) +
                 (((size_t)b * HH + h) * TT + t0) * DD;

    const int tid = threadIdx.y * 16 + threadIdx.x;
    for (int i = tid; i < TILE * CC; i += 256) {
        int r = i >> 6, c = i & 63;
        a_s[r][c] = src[i];
        w_s[r][c] = W[i];
    }
    __syncthreads();

    const int r0 = threadIdx.y * 4, c0 = threadIdx.x * 4;
    float acc[4][4] = {};
#pragma unroll 8
    for (int c = 0; c < CC; c++) {
        float av[4], wv[4];
#pragma unroll
        for (int i = 0; i < 4; i++) av[i] = a_s[r0 + i][c];
#pragma unroll
        for (int j = 0; j < 4; j++) wv[j] = w_s[c][c0 + j];
#pragma unroll
        for (int i = 0; i < 4; i++)
#pragma unroll
            for (int j = 0; j < 4; j++) acc[i][j] = fmaf(av[i], wv[j], acc[i][j]);
    }

#pragma unroll
    for (int i = 0; i < 4; i++) {
        float4 o4 = make_float4(acc[i][0], acc[i][1], acc[i][2], acc[i][3]);
        *reinterpret_cast<float4*>(out + (size_t)(r0 + i) * DD + c0) = o4;
    }
}

// ---------------------------------------------------------------------------
// Kernel 2: causal flash attention. grid (T/64, B*H), block (16,16)
// Online softmax, 64x64 tiles, fp32.
// ---------------------------------------------------------------------------
__global__ void attn_kernel() {
    extern __shared__ float smem[];
    float (*q_s)[PAD]  = reinterpret_cast<float(*)[PAD]>(smem);
    float (*kT_s)[PAD] = reinterpret_cast<float(*)[PAD]>(smem + TILE * PAD);
    float (*v_s)[PAD]  = reinterpret_cast<float(*)[PAD]>(smem + 2 * TILE * PAD);
    float (*p_s)[PAD]  = reinterpret_cast<float(*)[PAD]>(smem + 3 * TILE * PAD);

    const int qt = blockIdx.x;           // query tile
    const int bh = blockIdx.y;
    const int tid = threadIdx.y * 16 + threadIdx.x;
    const int r0 = threadIdx.y * 4, c0 = threadIdx.x * 4;
    const float scale = 0.125f;          // D^-0.5

    const float* qptr = g_q + (((size_t)bh) * TT + (size_t)qt * TILE) * DD;

    // Load Q tile once
    for (int i = tid; i < TILE * DD; i += 256) {
        int r = i >> 6, d = i & 63;
        q_s[r][d] = qptr[i];
    }

    float m[4], l[4], acc[4][4];
#pragma unroll
    for (int i = 0; i < 4; i++) { m[i] = NEG_BIG; l[i] = 0.0f; }
#pragma unroll
    for (int i = 0; i < 4; i++)
#pragma unroll
        for (int j = 0; j < 4; j++) acc[i][j] = 0.0f;

    for (int jt = 0; jt <= qt; jt++) {
        __syncthreads();
        const float* kptr = g_k + (((size_t)bh) * TT + (size_t)jt * TILE) * DD;
        const float* vptr = g_v + (((size_t)bh) * TT + (size_t)jt * TILE) * DD;
        // Load K transposed (conflict-free: consecutive d -> consecutive banks)
        for (int i = tid; i < TILE * DD; i += 256) {
            int key = i >> 6, d = i & 63;
            kT_s[d][key] = kptr[i];
            v_s[key][d]  = vptr[i];
        }
        __syncthreads();

        // S = Q K^T (scaled), 4x4 per thread
        float sreg[4][4] = {};
#pragma unroll 8
        for (int d = 0; d < DD; d++) {
            float qv[4], kv[4];
#pragma unroll
            for (int i = 0; i < 4; i++) qv[i] = q_s[r0 + i][d];
#pragma unroll
            for (int j = 0; j < 4; j++) kv[j] = kT_s[d][c0 + j];
#pragma unroll
            for (int i = 0; i < 4; i++)
#pragma unroll
                for (int j = 0; j < 4; j++) sreg[i][j] = fmaf(qv[i], kv[j], sreg[i][j]);
        }
#pragma unroll
        for (int i = 0; i < 4; i++)
#pragma unroll
            for (int j = 0; j < 4; j++) sreg[i][j] *= scale;

        // Causal mask on diagonal tile: key (c0+j) > query (r0+i) -> -inf
        if (jt == qt) {
#pragma unroll
            for (int i = 0; i < 4; i++)
#pragma unroll
                for (int j = 0; j < 4; j++)
                    if (c0 + j > r0 + i) sreg[i][j] = NEG_BIG;
        }

        // Row max across the 16 threads sharing each row
        float mloc[4];
#pragma unroll
        for (int i = 0; i < 4; i++) {
            float mm = sreg[i][0];
            mm = fmaxf(mm, sreg[i][1]);
            mm = fmaxf(mm, sreg[i][2]);
            mm = fmaxf(mm, sreg[i][3]);
#pragma unroll
            for (int w = 1; w < 16; w <<= 1)
                mm = fmaxf(mm, __shfl_xor_sync(0xffffffffu, mm, w));
            mloc[i] = mm;
        }

        float corr[4];
#pragma unroll
        for (int i = 0; i < 4; i++) {
            float mnew = fmaxf(m[i], mloc[i]);
            corr[i] = __expf(m[i] - mnew);
            m[i] = mnew;
        }

        // P = exp(S - m), row sums
        float ps[4];
#pragma unroll
        for (int i = 0; i < 4; i++) {
            float s = 0.0f;
#pragma unroll
            for (int j = 0; j < 4; j++) {
                float p = __expf(sreg[i][j] - m[i]);
                sreg[i][j] = p;
                s += p;
            }
#pragma unroll
            for (int w = 1; w < 16; w <<= 1)
                s += __shfl_xor_sync(0xffffffffu, s, w);
            ps[i] = s;
        }

#pragma unroll
        for (int i = 0; i < 4; i++) {
            l[i] = l[i] * corr[i] + ps[i];
#pragma unroll
            for (int j = 0; j < 4; j++) acc[i][j] *= corr[i];
        }

        // Write P to smem for the PV GEMM
#pragma unroll
        for (int i = 0; i < 4; i++)
#pragma unroll
            for (int j = 0; j < 4; j++) p_s[r0 + i][c0 + j] = sreg[i][j];
        __syncthreads();

        // O += P V
#pragma unroll 8
        for (int s = 0; s < TILE; s++) {
            float pv[4], vv[4];
#pragma unroll
            for (int i = 0; i < 4; i++) pv[i] = p_s[r0 + i][s];
#pragma unroll
            for (int j = 0; j < 4; j++) vv[j] = v_s[s][c0 + j];
#pragma unroll
            for (int i = 0; i < 4; i++)
#pragma unroll
                for (int j = 0; j < 4; j++) acc[i][j] = fmaf(pv[i], vv[j], acc[i][j]);
        }
    }

    // Normalize and store
    float* optr = g_o + (((size_t)bh) * TT + (size_t)qt * TILE) * DD;
#pragma unroll
    for (int i = 0; i < 4; i++) {
        float inv = 1.0f / l[i];
        float4 o4 = make_float4(acc[i][0] * inv, acc[i][1] * inv,
                                acc[i][2] * inv, acc[i][3] * inv);
        *reinterpret_cast<float4*>(optr + (size_t)(r0 + i) * DD + c0) = o4;
    }
}

// ---------------------------------------------------------------------------
// Kernel 3: output projection. grid (T/64, B), block (16,16)
// out[b,t,c] = sum_{h,d} O[b,h,t,d] * W_proj[h*D+d, c] + b_proj[c]
// ---------------------------------------------------------------------------
__global__ void proj_kernel(const float* __restrict__ W_proj,
                            const float* __restrict__ b_proj,
                            float* __restrict__ out) {
    __shared__ float a_s[TILE][PAD];
    __shared__ float w_s[TILE][PAD];

    const int b  = blockIdx.y;
    const int t0 = blockIdx.x * TILE;
    const int tid = threadIdx.y * 16 + threadIdx.x;
    const int r0 = threadIdx.y * 4, c0 = threadIdx.x * 4;

    float acc[4][4] = {};
    for (int h = 0; h < HH; h++) {
        __syncthreads();
        const float* aptr = g_o + (((size_t)b * HH + h) * TT + t0) * DD;
        const float* wptr = W_proj + (size_t)h * DD * CC;
        for (int i = tid; i < TILE * DD; i += 256) {
            int r = i >> 6, c = i & 63;
            a_s[r][c] = aptr[i];
            w_s[r][c] = wptr[i];
        }
        __syncthreads();
#pragma unroll 8
        for (int d = 0; d < DD; d++) {
            float av[4], wv[4];
#pragma unroll
            for (int i = 0; i < 4; i++) av[i] = a_s[r0 + i][d];
#pragma unroll
            for (int j = 0; j < 4; j++) wv[j] = w_s[d][c0 + j];
#pragma unroll
            for (int i = 0; i < 4; i++)
#pragma unroll
                for (int j = 0; j < 4; j++) acc[i][j] = fmaf(av[i], wv[j], acc[i][j]);
        }
    }

    float bp[4];
#pragma unroll
    for (int j = 0; j < 4; j++) bp[j] = b_proj[c0 + j];

    float* optr = out + ((size_t)b * TT + t0) * CC;
#pragma unroll
    for (int i = 0; i < 4; i++) {
        float4 o4 = make_float4(acc[i][0] + bp[0], acc[i][1] + bp[1],
                                acc[i][2] + bp[2], acc[i][3] + bp[3]);
        *reinterpret_cast<float4*>(optr + (size_t)(r0 + i) * CC + c0) = o4;
    }
}

// ---------------------------------------------------------------------------
extern "C" void kernel_launch(void* const* d_in, const int* in_sizes, int n_in,
                              void* d_out, int out_size) {
    const float* x      = (const float*)d_in[0];
    const float* y      = (const float*)d_in[1];
    const float* Wq     = (const float*)d_in[2];
    const float* Wk     = (const float*)d_in[3];
    const float* Wv     = (const float*)d_in[4];
    const float* W_proj = (const float*)d_in[5];
    const float* b_proj = (const float*)d_in[6];
    float* out = (float*)d_out;

    (void)in_sizes; (void)n_in; (void)out_size;

    static int smem_set = 0;
    const int attn_smem = 4 * TILE * PAD * sizeof(float);  // 66560 B
    if (!smem_set) {
        cudaFuncSetAttribute(attn_kernel,
                             cudaFuncAttributeMaxDynamicSharedMemorySize, attn_smem);
        smem_set = 1;
    }

    dim3 blk(16, 16);
    qkv_kernel<<<dim3(TT / TILE, BB * HH, 3), blk>>>(x, y, Wq, Wk, Wv);
    attn_kernel<<<dim3(TT / TILE, BB * HH), blk, attn_smem>>>();
    proj_kernel<<<dim3(TT / TILE, BB), blk>>>(W_proj, b_proj, out);
}

// round 3
// speedup vs baseline: 2.3750x; 2.3750x over previous
#include <cuda_runtime.h>
#include <cuda_bf16.h>
#include <cstdint>

#define BB 4
#define TT 2048
#define CC 64
#define HH 6
#define DD 64
#define BH (BB*HH)
#define NEG_BIG (-1e30f)

// ---------------------------------------------------------------------------
// Scratch (__device__ globals; allocation-free rule)
// ---------------------------------------------------------------------------
__device__ __nv_bfloat16 g_qhi[(size_t)BH*TT*DD];
__device__ __nv_bfloat16 g_qlo[(size_t)BH*TT*DD];
__device__ __nv_bfloat16 g_khi[(size_t)BH*TT*DD];
__device__ __nv_bfloat16 g_klo[(size_t)BH*TT*DD];
__device__ __nv_bfloat16 g_vthi[(size_t)BH*DD*TT];   // transposed: [bh][d][t]
__device__ __nv_bfloat16 g_vtlo[(size_t)BH*DD*TT];
__device__ float g_o[(size_t)BH*TT*DD];

__device__ __forceinline__ uint32_t smem_u32(const void* p) {
    uint32_t a;
    asm("{ .reg .u64 t; cvta.to.shared.u64 t, %1; cvt.u32.u64 %0, t; }"
        : "=r"(a) : "l"(p));
    return a;
}

#define LDMATRIX_X4(r0, r1, r2, r3, addr) \
    asm volatile("ldmatrix.sync.aligned.m8n8.x4.shared.b16 {%0,%1,%2,%3}, [%4];" \
        : "=r"(r0), "=r"(r1), "=r"(r2), "=r"(r3) : "r"(addr))

#define MMA_BF16(d0, d1, d2, d3, a0, a1, a2, a3, b0, b1) \
    asm volatile("mma.sync.aligned.m16n8k16.row.col.f32.bf16.bf16.f32 " \
        "{%0,%1,%2,%3}, {%4,%5,%6,%7}, {%8,%9}, {%0,%1,%2,%3};" \
        : "+f"(d0), "+f"(d1), "+f"(d2), "+f"(d3) \
        : "r"(a0), "r"(a1), "r"(a2), "r"(a3), "r"(b0), "r"(b1))

__device__ __forceinline__ uint32_t pack_bf16x2(__nv_bfloat16 a, __nv_bfloat16 b) {
    return (uint32_t)__bfloat16_as_ushort(a) | ((uint32_t)__bfloat16_as_ushort(b) << 16);
}
__device__ __forceinline__ void split_pack(float a, float b, uint32_t& hi, uint32_t& lo) {
    __nv_bfloat16 ah = __float2bfloat16(a);
    __nv_bfloat16 bh = __float2bfloat16(b);
    __nv_bfloat16 al = __float2bfloat16(a - __bfloat162float(ah));
    __nv_bfloat16 bl = __float2bfloat16(b - __bfloat162float(bh));
    hi = pack_bf16x2(ah, bh);
    lo = pack_bf16x2(al, bl);
}

// ---------------------------------------------------------------------------
// Kernel 1: QKV projection (fp32 SIMT) + bf16 hi/lo split + V transpose.
// grid (TT/128, BH, 3), block (16,16).
// ---------------------------------------------------------------------------
__global__ void qkv_kernel(const float* __restrict__ x, const float* __restrict__ y,
                           const float* __restrict__ Wq, const float* __restrict__ Wk,
                           const float* __restrict__ Wv) {
    __shared__ __align__(16) float a_s[128][65];
    __shared__ __align__(16) float w_s[64][64];

    const int sel = blockIdx.z;
    const int bh  = blockIdx.y;
    const int b   = bh / HH, h = bh % HH;
    const int t0  = blockIdx.x * 128;

    const float* src = (sel == 0 ? x : y) + ((size_t)b * TT + t0) * CC;
    const float* W   = (sel == 0 ? Wq : (sel == 1 ? Wk : Wv)) + (size_t)h * CC * DD;

    const int tx = threadIdx.x, ty = threadIdx.y;
    const int tid = ty * 16 + tx;
    const int c0 = tx * 4;

    for (int i = tid; i < 2048; i += 256) {
        int r = i >> 4, c4 = (i & 15) << 2;
        float4 v = reinterpret_cast<const float4*>(src)[i];
        a_s[r][c4] = v.x; a_s[r][c4+1] = v.y; a_s[r][c4+2] = v.z; a_s[r][c4+3] = v.w;
    }
    for (int i = tid; i < 1024; i += 256) {
        int r = i >> 4, c4 = (i & 15) << 2;
        *reinterpret_cast<float4*>(&w_s[r][c4]) = reinterpret_cast<const float4*>(W)[i];
    }
    __syncthreads();

    float acc[8][4] = {};
#pragma unroll 8
    for (int c = 0; c < CC; c++) {
        float4 wv = *reinterpret_cast<const float4*>(&w_s[c][c0]);
#pragma unroll
        for (int i = 0; i < 8; i++) {
            float av = a_s[ty + 16 * i][c];
            acc[i][0] = fmaf(av, wv.x, acc[i][0]);
            acc[i][1] = fmaf(av, wv.y, acc[i][1]);
            acc[i][2] = fmaf(av, wv.z, acc[i][2]);
            acc[i][3] = fmaf(av, wv.w, acc[i][3]);
        }
    }

    if (sel < 2) {
        __nv_bfloat16* ghi = (sel == 0 ? g_qhi : g_khi);
        __nv_bfloat16* glo = (sel == 0 ? g_qlo : g_klo);
#pragma unroll
        for (int i = 0; i < 8; i++) {
            int t = t0 + ty + 16 * i;
            size_t base = ((size_t)bh * TT + t) * DD + c0;
            uint32_t h0, l0, h1, l1;
            split_pack(acc[i][0], acc[i][1], h0, l0);
            split_pack(acc[i][2], acc[i][3], h1, l1);
            *reinterpret_cast<uint2*>(ghi + base) = make_uint2(h0, h1);
            *reinterpret_cast<uint2*>(glo + base) = make_uint2(l0, l1);
        }
    } else {
        __syncthreads();
        __nv_bfloat16* vs = reinterpret_cast<__nv_bfloat16*>(&a_s[0][0]);
#pragma unroll
        for (int i = 0; i < 8; i++) {
            int key = ty + 16 * i;
#pragma unroll
            for (int j = 0; j < 4; j++) {
                int d = c0 + j;
                float v = acc[i][j];
                __nv_bfloat16 hv = __float2bfloat16(v);
                __nv_bfloat16 lv = __float2bfloat16(v - __bfloat162float(hv));
                vs[d * 128 + key] = hv;
                vs[8192 + d * 128 + key] = lv;
            }
        }
        __syncthreads();
        for (int u = tid; u < 1024; u += 256) {
            int d = u >> 4, g = u & 15;
            uint4 hv = *reinterpret_cast<uint4*>(vs + d * 128 + g * 8);
            uint4 lv = *reinterpret_cast<uint4*>(vs + 8192 + d * 128 + g * 8);
            size_t dst = ((size_t)bh * DD + d) * TT + t0 + g * 8;
            *reinterpret_cast<uint4*>(g_vthi + dst) = hv;
            *reinterpret_cast<uint4*>(g_vtlo + dst) = lv;
        }
    }
}

// ---------------------------------------------------------------------------
// Kernel 2: causal flash attention via mma.sync (bf16 hi/lo, 3 chains).
// grid (TT/64, BH), block 128 (4 warps x m16 rows).
// ---------------------------------------------------------------------------
#define KSTRIDE 72   // bf16 elements per smem row (conflict-free for ldmatrix)

__global__ void __launch_bounds__(128) attn_mma_kernel() {
    __shared__ __align__(16) __nv_bfloat16 skhi[64 * KSTRIDE];
    __shared__ __align__(16) __nv_bfloat16 sklo[64 * KSTRIDE];
    __shared__ __align__(16) __nv_bfloat16 svhi[64 * KSTRIDE];
    __shared__ __align__(16) __nv_bfloat16 svlo[64 * KSTRIDE];

    const int tid  = threadIdx.x;
    const int wid  = tid >> 5, lane = tid & 31;
    const int g    = lane >> 2, tg = lane & 3;
    const int qt   = blockIdx.x, bh = blockIdx.y;
    const int q0   = qt * 64;
    const int wrow = wid * 16;

    const uint32_t skhi_b = smem_u32(skhi);
    const uint32_t sklo_b = smem_u32(sklo);
    const uint32_t svhi_b = smem_u32(svhi);
    const uint32_t svlo_b = smem_u32(svlo);

    // --- Q fragments (loaded once, straight from gmem) ---
    uint32_t qh[4][4], ql[4][4];
    {
        const __nv_bfloat16* qbh = g_qhi + ((size_t)bh * TT + q0 + wrow) * DD;
        const __nv_bfloat16* qbl = g_qlo + ((size_t)bh * TT + q0 + wrow) * DD;
#pragma unroll
        for (int t = 0; t < 4; t++) {
            int col0 = t * 16 + tg * 2;
            qh[t][0] = *reinterpret_cast<const uint32_t*>(qbh + (size_t)g * DD + col0);
            qh[t][1] = *reinterpret_cast<const uint32_t*>(qbh + (size_t)(g + 8) * DD + col0);
            qh[t][2] = *reinterpret_cast<const uint32_t*>(qbh + (size_t)g * DD + col0 + 8);
            qh[t][3] = *reinterpret_cast<const uint32_t*>(qbh + (size_t)(g + 8) * DD + col0 + 8);
            ql[t][0] = *reinterpret_cast<const uint32_t*>(qbl + (size_t)g * DD + col0);
            ql[t][1] = *reinterpret_cast<const uint32_t*>(qbl + (size_t)(g + 8) * DD + col0);
            ql[t][2] = *reinterpret_cast<const uint32_t*>(qbl + (size_t)g * DD + col0 + 8);
            ql[t][3] = *reinterpret_cast<const uint32_t*>(qbl + (size_t)(g + 8) * DD + col0 + 8);
        }
    }

    float o[8][4];
#pragma unroll
    for (int j = 0; j < 8; j++)
#pragma unroll
        for (int e = 0; e < 4; e++) o[j][e] = 0.0f;
    float m0 = NEG_BIG, m1 = NEG_BIG, l0 = 0.0f, l1 = 0.0f;
    const int row0 = q0 + wrow + g, row1 = row0 + 8;
    const float scale = 0.125f;

    // ldmatrix lane addressing (row within 8-row group, matrix index)
    const int lrow = lane & 7;
    const int lmi  = lane >> 3;   // 0..3

    for (int jt = 0; jt <= qt; jt++) {
        const int j0 = jt * 64;

        // --- stage K hi/lo and V^T hi/lo tiles ---
        {
            const __nv_bfloat16* kh = g_khi + ((size_t)bh * TT + j0) * DD;
            const __nv_bfloat16* kl = g_klo + ((size_t)bh * TT + j0) * DD;
            const __nv_bfloat16* vh = g_vthi + (size_t)bh * DD * TT + j0;
            const __nv_bfloat16* vl = g_vtlo + (size_t)bh * DD * TT + j0;
#pragma unroll
            for (int u = tid; u < 512; u += 128) {
                int r = u >> 3, ch = (u & 7) * 8;
                *reinterpret_cast<uint4*>(skhi + r * KSTRIDE + ch) =
                    *reinterpret_cast<const uint4*>(kh + (size_t)r * DD + ch);
                *reinterpret_cast<uint4*>(sklo + r * KSTRIDE + ch) =
                    *reinterpret_cast<const uint4*>(kl + (size_t)r * DD + ch);
                *reinterpret_cast<uint4*>(svhi + r * KSTRIDE + ch) =
                    *reinterpret_cast<const uint4*>(vh + (size_t)r * TT + ch);
                *reinterpret_cast<uint4*>(svlo + r * KSTRIDE + ch) =
                    *reinterpret_cast<const uint4*>(vl + (size_t)r * TT + ch);
            }
        }
        __syncthreads();

        // --- S = Q K^T (3 chains) ---
        float c[8][4];
#pragma unroll
        for (int j = 0; j < 8; j++)
#pragma unroll
            for (int e = 0; e < 4; e++) c[j][e] = 0.0f;

#pragma unroll
        for (int j = 0; j < 8; j++) {
            uint32_t roff = (uint32_t)((j * 8 + lrow) * KSTRIDE + lmi * 8) * 2;
#pragma unroll
            for (int tp = 0; tp < 2; tp++) {
                uint32_t coff = roff + (uint32_t)(tp * 32) * 2;
                uint32_t kh0, kh1, kh2, kh3, kl0, kl1, kl2, kl3;
                LDMATRIX_X4(kh0, kh1, kh2, kh3, skhi_b + coff);
                LDMATRIX_X4(kl0, kl1, kl2, kl3, sklo_b + coff);
                int t0s = 2 * tp, t1s = 2 * tp + 1;
                MMA_BF16(c[j][0], c[j][1], c[j][2], c[j][3],
                         qh[t0s][0], qh[t0s][1], qh[t0s][2], qh[t0s][3], kh0, kh1);
                MMA_BF16(c[j][0], c[j][1], c[j][2], c[j][3],
                         qh[t1s][0], qh[t1s][1], qh[t1s][2], qh[t1s][3], kh2, kh3);
                MMA_BF16(c[j][0], c[j][1], c[j][2], c[j][3],
                         qh[t0s][0], qh[t0s][1], qh[t0s][2], qh[t0s][3], kl0, kl1);
                MMA_BF16(c[j][0], c[j][1], c[j][2], c[j][3],
                         qh[t1s][0], qh[t1s][1], qh[t1s][2], qh[t1s][3], kl2, kl3);
                MMA_BF16(c[j][0], c[j][1], c[j][2], c[j][3],
                         ql[t0s][0], ql[t0s][1], ql[t0s][2], ql[t0s][3], kh0, kh1);
                MMA_BF16(c[j][0], c[j][1], c[j][2], c[j][3],
                         ql[t1s][0], ql[t1s][1], ql[t1s][2], ql[t1s][3], kh2, kh3);
            }
        }

        // --- softmax (mma C-layout; rows g and g+8) ---
        const bool diag = (jt == qt);
        float mx0 = NEG_BIG, mx1 = NEG_BIG;
#pragma unroll
        for (int j = 0; j < 8; j++) {
#pragma unroll
            for (int e = 0; e < 2; e++) {
                int col = j0 + j * 8 + tg * 2 + e;
                float v0 = c[j][e] * scale;
                float v1 = c[j][2 + e] * scale;
                if (diag && col > row0) v0 = NEG_BIG;
                if (diag && col > row1) v1 = NEG_BIG;
                c[j][e] = v0; c[j][2 + e] = v1;
                mx0 = fmaxf(mx0, v0); mx1 = fmaxf(mx1, v1);
            }
        }
        mx0 = fmaxf(mx0, __shfl_xor_sync(0xffffffffu, mx0, 1));
        mx0 = fmaxf(mx0, __shfl_xor_sync(0xffffffffu, mx0, 2));
        mx1 = fmaxf(mx1, __shfl_xor_sync(0xffffffffu, mx1, 1));
        mx1 = fmaxf(mx1, __shfl_xor_sync(0xffffffffu, mx1, 2));

        float mn0 = fmaxf(m0, mx0), mn1 = fmaxf(m1, mx1);
        float corr0 = __expf(m0 - mn0), corr1 = __expf(m1 - mn1);
        m0 = mn0; m1 = mn1;

        float s0 = 0.0f, s1 = 0.0f;
#pragma unroll
        for (int j = 0; j < 8; j++) {
#pragma unroll
            for (int e = 0; e < 2; e++) {
                float p0 = __expf(c[j][e] - mn0);
                float p1 = __expf(c[j][2 + e] - mn1);
                c[j][e] = p0; c[j][2 + e] = p1;
                s0 += p0; s1 += p1;
            }
        }
        s0 += __shfl_xor_sync(0xffffffffu, s0, 1);
        s0 += __shfl_xor_sync(0xffffffffu, s0, 2);
        s1 += __shfl_xor_sync(0xffffffffu, s1, 1);
        s1 += __shfl_xor_sync(0xffffffffu, s1, 2);
        l0 = l0 * corr0 + s0;
        l1 = l1 * corr1 + s1;

#pragma unroll
        for (int j = 0; j < 8; j++) {
            o[j][0] *= corr0; o[j][1] *= corr0;
            o[j][2] *= corr1; o[j][3] *= corr1;
        }

        // --- P fragments from S accumulators (register repack) ---
        uint32_t ph[4][4], pl[4][4];
#pragma unroll
        for (int t = 0; t < 4; t++) {
            split_pack(c[2 * t][0],     c[2 * t][1],     ph[t][0], pl[t][0]);
            split_pack(c[2 * t][2],     c[2 * t][3],     ph[t][1], pl[t][1]);
            split_pack(c[2 * t + 1][0], c[2 * t + 1][1], ph[t][2], pl[t][2]);
            split_pack(c[2 * t + 1][2], c[2 * t + 1][3], ph[t][3], pl[t][3]);
        }

        // --- O += P V (3 chains), V^T tile in smem ---
#pragma unroll
        for (int j = 0; j < 8; j++) {
            uint32_t roff = (uint32_t)((j * 8 + lrow) * KSTRIDE + lmi * 8) * 2;
#pragma unroll
            for (int tp = 0; tp < 2; tp++) {
                uint32_t coff = roff + (uint32_t)(tp * 32) * 2;
                uint32_t vh0, vh1, vh2, vh3, vl0, vl1, vl2, vl3;
                LDMATRIX_X4(vh0, vh1, vh2, vh3, svhi_b + coff);
                LDMATRIX_X4(vl0, vl1, vl2, vl3, svlo_b + coff);
                int t0s = 2 * tp, t1s = 2 * tp + 1;
                MMA_BF16(o[j][0], o[j][1], o[j][2], o[j][3],
                         ph[t0s][0], ph[t0s][1], ph[t0s][2], ph[t0s][3], vh0, vh1);
                MMA_BF16(o[j][0], o[j][1], o[j][2], o[j][3],
                         ph[t1s][0], ph[t1s][1], ph[t1s][2], ph[t1s][3], vh2, vh3);
                MMA_BF16(o[j][0], o[j][1], o[j][2], o[j][3],
                         ph[t0s][0], ph[t0s][1], ph[t0s][2], ph[t0s][3], vl0, vl1);
                MMA_BF16(o[j][0], o[j][1], o[j][2], o[j][3],
                         ph[t1s][0], ph[t1s][1], ph[t1s][2], ph[t1s][3], vl2, vl3);
                MMA_BF16(o[j][0], o[j][1], o[j][2], o[j][3],
                         pl[t0s][0], pl[t0s][1], pl[t0s][2], pl[t0s][3], vh0, vh1);
                MMA_BF16(o[j][0], o[j][1], o[j][2], o[j][3],
                         pl[t1s][0], pl[t1s][1], pl[t1s][2], pl[t1s][3], vh2, vh3);
            }
        }
        __syncthreads();
    }

    // --- normalize + store ---
    {
        float inv0 = 1.0f / l0, inv1 = 1.0f / l1;
        float* op = g_o + ((size_t)bh * TT + q0 + wrow) * DD;
#pragma unroll
        for (int j = 0; j < 8; j++) {
            int col = j * 8 + tg * 2;
            *reinterpret_cast<float2*>(op + (size_t)g * DD + col) =
                make_float2(o[j][0] * inv0, o[j][1] * inv0);
            *reinterpret_cast<float2*>(op + (size_t)(g + 8) * DD + col) =
                make_float2(o[j][2] * inv1, o[j][3] * inv1);
        }
    }
}

// ---------------------------------------------------------------------------
// Kernel 3: output projection. grid (TT/64, BB), block (16,16)
// ---------------------------------------------------------------------------
__global__ void proj_kernel(const float* __restrict__ W_proj,
                            const float* __restrict__ b_proj,
                            float* __restrict__ out) {
    __shared__ __align__(16) float a_s[64][65];
    __shared__ __align__(16) float w_s[64][64];

    const int b  = blockIdx.y;
    const int t0 = blockIdx.x * 64;
    const int tx = threadIdx.x, ty = threadIdx.y;
    const int tid = ty * 16 + tx;
    const int c0 = tx * 4;

    float acc[4][4] = {};
    for (int h = 0; h < HH; h++) {
        __syncthreads();
        const float* aptr = g_o + (((size_t)b * HH + h) * TT + t0) * DD;
        const float* wptr = W_proj + (size_t)h * DD * CC;
        for (int i = tid; i < 1024; i += 256) {
            int r = i >> 4, c4 = (i & 15) << 2;
            float4 v = reinterpret_cast<const float4*>(aptr)[i];
            a_s[r][c4] = v.x; a_s[r][c4+1] = v.y; a_s[r][c4+2] = v.z; a_s[r][c4+3] = v.w;
            *reinterpret_cast<float4*>(&w_s[r][c4]) = reinterpret_cast<const float4*>(wptr)[i];
        }
        __syncthreads();
#pragma unroll 8
        for (int d = 0; d < DD; d++) {
            float4 wv = *reinterpret_cast<const float4*>(&w_s[d][c0]);
#pragma unroll
            for (int i = 0; i < 4; i++) {
                float av = a_s[ty + 16 * i][d];
                acc[i][0] = fmaf(av, wv.x, acc[i][0]);
                acc[i][1] = fmaf(av, wv.y, acc[i][1]);
                acc[i][2] = fmaf(av, wv.z, acc[i][2]);
                acc[i][3] = fmaf(av, wv.w, acc[i][3]);
            }
        }
    }

    float bp0 = b_proj[c0], bp1 = b_proj[c0+1], bp2 = b_proj[c0+2], bp3 = b_proj[c0+3];
    float* optr = out + ((size_t)b * TT + t0) * CC;
#pragma unroll
    for (int i = 0; i < 4; i++) {
        float4 o4 = make_float4(acc[i][0] + bp0, acc[i][1] + bp1,
                                acc[i][2] + bp2, acc[i][3] + bp3);
        *reinterpret_cast<float4*>(optr + (size_t)(ty + 16 * i) * CC + c0) = o4;
    }
}

// ---------------------------------------------------------------------------
extern "C" void kernel_launch(void* const* d_in, const int* in_sizes, int n_in,
                              void* d_out, int out_size) {
    const float* x      = (const float*)d_in[0];
    const float* y      = (const float*)d_in[1];
    const float* Wq     = (const float*)d_in[2];
    const float* Wk     = (const float*)d_in[3];
    const float* Wv     = (const float*)d_in[4];
    const float* W_proj = (const float*)d_in[5];
    const float* b_proj = (const float*)d_in[6];
    float* out = (float*)d_out;
    (void)in_sizes; (void)n_in; (void)out_size;

    qkv_kernel<<<dim3(TT / 128, BH, 3), dim3(16, 16)>>>(x, y, Wq, Wk, Wv);
    attn_mma_kernel<<<dim3(TT / 64, BH), 128>>>();
    proj_kernel<<<dim3(TT / 64, BB), dim3(16, 16)>>>(W_proj, b_proj, out);
}

// round 4
// speedup vs baseline: 2.3772x; 1.0009x over previous
#include <cuda_runtime.h>
#include <cuda_bf16.h>
#include <cstdint>

#define BB 4
#define TT 2048
#define CC 64
#define HH 6
#define DD 64
#define BH (BB*HH)
#define NEG_BIG (-1e30f)

// ---------------------------------------------------------------------------
// Scratch (__device__ globals; allocation-free rule)
// ---------------------------------------------------------------------------
__device__ __nv_bfloat16 g_qhi[(size_t)BH*TT*DD];
__device__ __nv_bfloat16 g_qlo[(size_t)BH*TT*DD];
__device__ __nv_bfloat16 g_khi[(size_t)BH*TT*DD];
__device__ __nv_bfloat16 g_klo[(size_t)BH*TT*DD];
__device__ __nv_bfloat16 g_vthi[(size_t)BH*DD*TT];   // transposed: [bh][d][t]
__device__ __nv_bfloat16 g_vtlo[(size_t)BH*DD*TT];
__device__ float g_o[(size_t)BH*TT*DD];

__device__ __forceinline__ uint32_t smem_u32(const void* p) {
    uint32_t a;
    asm("{ .reg .u64 t; cvta.to.shared.u64 t, %1; cvt.u32.u64 %0, t; }"
        : "=r"(a) : "l"(p));
    return a;
}

#define LDMATRIX_X4(r0, r1, r2, r3, addr) \
    asm volatile("ldmatrix.sync.aligned.m8n8.x4.shared.b16 {%0,%1,%2,%3}, [%4];" \
        : "=r"(r0), "=r"(r1), "=r"(r2), "=r"(r3) : "r"(addr))

#define MMA_BF16(d0, d1, d2, d3, a0, a1, a2, a3, b0, b1) \
    asm volatile("mma.sync.aligned.m16n8k16.row.col.f32.bf16.bf16.f32 " \
        "{%0,%1,%2,%3}, {%4,%5,%6,%7}, {%8,%9}, {%0,%1,%2,%3};" \
        : "+f"(d0), "+f"(d1), "+f"(d2), "+f"(d3) \
        : "r"(a0), "r"(a1), "r"(a2), "r"(a3), "r"(b0), "r"(b1))

__device__ __forceinline__ uint32_t pack_bf16x2(__nv_bfloat16 a, __nv_bfloat16 b) {
    return (uint32_t)__bfloat16_as_ushort(a) | ((uint32_t)__bfloat16_as_ushort(b) << 16);
}
__device__ __forceinline__ void split_pack(float a, float b, uint32_t& hi, uint32_t& lo) {
    __nv_bfloat16 ah = __float2bfloat16(a);
    __nv_bfloat16 bh = __float2bfloat16(b);
    __nv_bfloat16 al = __float2bfloat16(a - __bfloat162float(ah));
    __nv_bfloat16 bl = __float2bfloat16(b - __bfloat162float(bh));
    hi = pack_bf16x2(ah, bh);
    lo = pack_bf16x2(al, bl);
}

// ---------------------------------------------------------------------------
// Kernel 1: QKV projection (fp32 SIMT) + bf16 hi/lo split + V transpose.
// grid (TT/128, BH, 3), block (16,16).
// ---------------------------------------------------------------------------
__global__ void qkv_kernel(const float* __restrict__ x, const float* __restrict__ y,
                           const float* __restrict__ Wq, const float* __restrict__ Wk,
                           const float* __restrict__ Wv) {
    __shared__ __align__(16) float a_s[128][65];
    __shared__ __align__(16) float w_s[64][64];

    const int sel = blockIdx.z;
    const int bh  = blockIdx.y;
    const int b   = bh / HH, h = bh % HH;
    const int t0  = blockIdx.x * 128;

    const float* src = (sel == 0 ? x : y) + ((size_t)b * TT + t0) * CC;
    const float* W   = (sel == 0 ? Wq : (sel == 1 ? Wk : Wv)) + (size_t)h * CC * DD;

    const int tx = threadIdx.x, ty = threadIdx.y;
    const int tid = ty * 16 + tx;
    const int c0 = tx * 4;

    for (int i = tid; i < 2048; i += 256) {
        int r = i >> 4, c4 = (i & 15) << 2;
        float4 v = reinterpret_cast<const float4*>(src)[i];
        a_s[r][c4] = v.x; a_s[r][c4+1] = v.y; a_s[r][c4+2] = v.z; a_s[r][c4+3] = v.w;
    }
    for (int i = tid; i < 1024; i += 256) {
        int r = i >> 4, c4 = (i & 15) << 2;
        *reinterpret_cast<float4*>(&w_s[r][c4]) = reinterpret_cast<const float4*>(W)[i];
    }
    __syncthreads();

    float acc[8][4] = {};
#pragma unroll 8
    for (int c = 0; c < CC; c++) {
        float4 wv = *reinterpret_cast<const float4*>(&w_s[c][c0]);
#pragma unroll
        for (int i = 0; i < 8; i++) {
            float av = a_s[ty + 16 * i][c];
            acc[i][0] = fmaf(av, wv.x, acc[i][0]);
            acc[i][1] = fmaf(av, wv.y, acc[i][1]);
            acc[i][2] = fmaf(av, wv.z, acc[i][2]);
            acc[i][3] = fmaf(av, wv.w, acc[i][3]);
        }
    }

    if (sel < 2) {
        __nv_bfloat16* ghi = (sel == 0 ? g_qhi : g_khi);
        __nv_bfloat16* glo = (sel == 0 ? g_qlo : g_klo);
#pragma unroll
        for (int i = 0; i < 8; i++) {
            int t = t0 + ty + 16 * i;
            size_t base = ((size_t)bh * TT + t) * DD + c0;
            uint32_t h0, l0, h1, l1;
            split_pack(acc[i][0], acc[i][1], h0, l0);
            split_pack(acc[i][2], acc[i][3], h1, l1);
            *reinterpret_cast<uint2*>(ghi + base) = make_uint2(h0, h1);
            *reinterpret_cast<uint2*>(glo + base) = make_uint2(l0, l1);
        }
    } else {
        __syncthreads();
        __nv_bfloat16* vs = reinterpret_cast<__nv_bfloat16*>(&a_s[0][0]);
#pragma unroll
        for (int i = 0; i < 8; i++) {
            int key = ty + 16 * i;
#pragma unroll
            for (int j = 0; j < 4; j++) {
                int d = c0 + j;
                float v = acc[i][j];
                __nv_bfloat16 hv = __float2bfloat16(v);
                __nv_bfloat16 lv = __float2bfloat16(v - __bfloat162float(hv));
                vs[d * 128 + key] = hv;
                vs[8192 + d * 128 + key] = lv;
            }
        }
        __syncthreads();
        for (int u = tid; u < 1024; u += 256) {
            int d = u >> 4, g = u & 15;
            uint4 hv = *reinterpret_cast<uint4*>(vs + d * 128 + g * 8);
            uint4 lv = *reinterpret_cast<uint4*>(vs + 8192 + d * 128 + g * 8);
            size_t dst = ((size_t)bh * DD + d) * TT + t0 + g * 8;
            *reinterpret_cast<uint4*>(g_vthi + dst) = hv;
            *reinterpret_cast<uint4*>(g_vtlo + dst) = lv;
        }
    }
}

// ---------------------------------------------------------------------------
// Kernel 2: causal flash attention via mma.sync (bf16 hi/lo, 3 chains).
// grid (TT/64, BH), block 128 (4 warps x m16 rows).
// ---------------------------------------------------------------------------
#define KSTRIDE 72   // bf16 elements per smem row (conflict-free for ldmatrix)

__global__ void __launch_bounds__(128) attn_mma_kernel() {
    __shared__ __align__(16) __nv_bfloat16 skhi[64 * KSTRIDE];
    __shared__ __align__(16) __nv_bfloat16 sklo[64 * KSTRIDE];
    __shared__ __align__(16) __nv_bfloat16 svhi[64 * KSTRIDE];
    __shared__ __align__(16) __nv_bfloat16 svlo[64 * KSTRIDE];

    const int tid  = threadIdx.x;
    const int wid  = tid >> 5, lane = tid & 31;
    const int g    = lane >> 2, tg = lane & 3;
    const int qt   = blockIdx.x, bh = blockIdx.y;
    const int q0   = qt * 64;
    const int wrow = wid * 16;

    const uint32_t skhi_b = smem_u32(skhi);
    const uint32_t sklo_b = smem_u32(sklo);
    const uint32_t svhi_b = smem_u32(svhi);
    const uint32_t svlo_b = smem_u32(svlo);

    // --- Q fragments (loaded once, straight from gmem) ---
    uint32_t qh[4][4], ql[4][4];
    {
        const __nv_bfloat16* qbh = g_qhi + ((size_t)bh * TT + q0 + wrow) * DD;
        const __nv_bfloat16* qbl = g_qlo + ((size_t)bh * TT + q0 + wrow) * DD;
#pragma unroll
        for (int t = 0; t < 4; t++) {
            int col0 = t * 16 + tg * 2;
            qh[t][0] = *reinterpret_cast<const uint32_t*>(qbh + (size_t)g * DD + col0);
            qh[t][1] = *reinterpret_cast<const uint32_t*>(qbh + (size_t)(g + 8) * DD + col0);
            qh[t][2] = *reinterpret_cast<const uint32_t*>(qbh + (size_t)g * DD + col0 + 8);
            qh[t][3] = *reinterpret_cast<const uint32_t*>(qbh + (size_t)(g + 8) * DD + col0 + 8);
            ql[t][0] = *reinterpret_cast<const uint32_t*>(qbl + (size_t)g * DD + col0);
            ql[t][1] = *reinterpret_cast<const uint32_t*>(qbl + (size_t)(g + 8) * DD + col0);
            ql[t][2] = *reinterpret_cast<const uint32_t*>(qbl + (size_t)g * DD + col0 + 8);
            ql[t][3] = *reinterpret_cast<const uint32_t*>(qbl + (size_t)(g + 8) * DD + col0 + 8);
        }
    }

    float o[8][4];
#pragma unroll
    for (int j = 0; j < 8; j++)
#pragma unroll
        for (int e = 0; e < 4; e++) o[j][e] = 0.0f;
    float m0 = NEG_BIG, m1 = NEG_BIG, l0 = 0.0f, l1 = 0.0f;
    const int row0 = q0 + wrow + g, row1 = row0 + 8;
    const float scale = 0.125f;

    // ldmatrix lane addressing (row within 8-row group, matrix index)
    const int lrow = lane & 7;
    const int lmi  = lane >> 3;   // 0..3

    for (int jt = 0; jt <= qt; jt++) {
        const int j0 = jt * 64;

        // --- stage K hi/lo and V^T hi/lo tiles ---
        {
            const __nv_bfloat16* kh = g_khi + ((size_t)bh * TT + j0) * DD;
            const __nv_bfloat16* kl = g_klo + ((size_t)bh * TT + j0) * DD;
            const __nv_bfloat16* vh = g_vthi + (size_t)bh * DD * TT + j0;
            const __nv_bfloat16* vl = g_vtlo + (size_t)bh * DD * TT + j0;
#pragma unroll
            for (int u = tid; u < 512; u += 128) {
                int r = u >> 3, ch = (u & 7) * 8;
                *reinterpret_cast<uint4*>(skhi + r * KSTRIDE + ch) =
                    *reinterpret_cast<const uint4*>(kh + (size_t)r * DD + ch);
                *reinterpret_cast<uint4*>(sklo + r * KSTRIDE + ch) =
                    *reinterpret_cast<const uint4*>(kl + (size_t)r * DD + ch);
                *reinterpret_cast<uint4*>(svhi + r * KSTRIDE + ch) =
                    *reinterpret_cast<const uint4*>(vh + (size_t)r * TT + ch);
                *reinterpret_cast<uint4*>(svlo + r * KSTRIDE + ch) =
                    *reinterpret_cast<const uint4*>(vl + (size_t)r * TT + ch);
            }
        }
        __syncthreads();

        // --- S = Q K^T (3 chains) ---
        float c[8][4];
#pragma unroll
        for (int j = 0; j < 8; j++)
#pragma unroll
            for (int e = 0; e < 4; e++) c[j][e] = 0.0f;

#pragma unroll
        for (int j = 0; j < 8; j++) {
            uint32_t roff = (uint32_t)((j * 8 + lrow) * KSTRIDE + lmi * 8) * 2;
#pragma unroll
            for (int tp = 0; tp < 2; tp++) {
                uint32_t coff = roff + (uint32_t)(tp * 32) * 2;
                uint32_t kh0, kh1, kh2, kh3, kl0, kl1, kl2, kl3;
                LDMATRIX_X4(kh0, kh1, kh2, kh3, skhi_b + coff);
                LDMATRIX_X4(kl0, kl1, kl2, kl3, sklo_b + coff);
                int t0s = 2 * tp, t1s = 2 * tp + 1;
                MMA_BF16(c[j][0], c[j][1], c[j][2], c[j][3],
                         qh[t0s][0], qh[t0s][1], qh[t0s][2], qh[t0s][3], kh0, kh1);
                MMA_BF16(c[j][0], c[j][1], c[j][2], c[j][3],
                         qh[t1s][0], qh[t1s][1], qh[t1s][2], qh[t1s][3], kh2, kh3);
                MMA_BF16(c[j][0], c[j][1], c[j][2], c[j][3],
                         qh[t0s][0], qh[t0s][1], qh[t0s][2], qh[t0s][3], kl0, kl1);
                MMA_BF16(c[j][0], c[j][1], c[j][2], c[j][3],
                         qh[t1s][0], qh[t1s][1], qh[t1s][2], qh[t1s][3], kl2, kl3);
                MMA_BF16(c[j][0], c[j][1], c[j][2], c[j][3],
                         ql[t0s][0], ql[t0s][1], ql[t0s][2], ql[t0s][3], kh0, kh1);
                MMA_BF16(c[j][0], c[j][1], c[j][2], c[j][3],
                         ql[t1s][0], ql[t1s][1], ql[t1s][2], ql[t1s][3], kh2, kh3);
            }
        }

        // --- softmax (mma C-layout; rows g and g+8) ---
        const bool diag = (jt == qt);
        float mx0 = NEG_BIG, mx1 = NEG_BIG;
#pragma unroll
        for (int j = 0; j < 8; j++) {
#pragma unroll
            for (int e = 0; e < 2; e++) {
                int col = j0 + j * 8 + tg * 2 + e;
                float v0 = c[j][e] * scale;
                float v1 = c[j][2 + e] * scale;
                if (diag && col > row0) v0 = NEG_BIG;
                if (diag && col > row1) v1 = NEG_BIG;
                c[j][e] = v0; c[j][2 + e] = v1;
                mx0 = fmaxf(mx0, v0); mx1 = fmaxf(mx1, v1);
            }
        }
        mx0 = fmaxf(mx0, __shfl_xor_sync(0xffffffffu, mx0, 1));
        mx0 = fmaxf(mx0, __shfl_xor_sync(0xffffffffu, mx0, 2));
        mx1 = fmaxf(mx1, __shfl_xor_sync(0xffffffffu, mx1, 1));
        mx1 = fmaxf(mx1, __shfl_xor_sync(0xffffffffu, mx1, 2));

        float mn0 = fmaxf(m0, mx0), mn1 = fmaxf(m1, mx1);
        float corr0 = __expf(m0 - mn0), corr1 = __expf(m1 - mn1);
        m0 = mn0; m1 = mn1;

        float s0 = 0.0f, s1 = 0.0f;
#pragma unroll
        for (int j = 0; j < 8; j++) {
#pragma unroll
            for (int e = 0; e < 2; e++) {
                float p0 = __expf(c[j][e] - mn0);
                float p1 = __expf(c[j][2 + e] - mn1);
                c[j][e] = p0; c[j][2 + e] = p1;
                s0 += p0; s1 += p1;
            }
        }
        s0 += __shfl_xor_sync(0xffffffffu, s0, 1);
        s0 += __shfl_xor_sync(0xffffffffu, s0, 2);
        s1 += __shfl_xor_sync(0xffffffffu, s1, 1);
        s1 += __shfl_xor_sync(0xffffffffu, s1, 2);
        l0 = l0 * corr0 + s0;
        l1 = l1 * corr1 + s1;

#pragma unroll
        for (int j = 0; j < 8; j++) {
            o[j][0] *= corr0; o[j][1] *= corr0;
            o[j][2] *= corr1; o[j][3] *= corr1;
        }

        // --- P fragments from S accumulators (register repack) ---
        uint32_t ph[4][4], pl[4][4];
#pragma unroll
        for (int t = 0; t < 4; t++) {
            split_pack(c[2 * t][0],     c[2 * t][1],     ph[t][0], pl[t][0]);
            split_pack(c[2 * t][2],     c[2 * t][3],     ph[t][1], pl[t][1]);
            split_pack(c[2 * t + 1][0], c[2 * t + 1][1], ph[t][2], pl[t][2]);
            split_pack(c[2 * t + 1][2], c[2 * t + 1][3], ph[t][3], pl[t][3]);
        }

        // --- O += P V (3 chains), V^T tile in smem ---
#pragma unroll
        for (int j = 0; j < 8; j++) {
            uint32_t roff = (uint32_t)((j * 8 + lrow) * KSTRIDE + lmi * 8) * 2;
#pragma unroll
            for (int tp = 0; tp < 2; tp++) {
                uint32_t coff = roff + (uint32_t)(tp * 32) * 2;
                uint32_t vh0, vh1, vh2, vh3, vl0, vl1, vl2, vl3;
                LDMATRIX_X4(vh0, vh1, vh2, vh3, svhi_b + coff);
                LDMATRIX_X4(vl0, vl1, vl2, vl3, svlo_b + coff);
                int t0s = 2 * tp, t1s = 2 * tp + 1;
                MMA_BF16(o[j][0], o[j][1], o[j][2], o[j][3],
                         ph[t0s][0], ph[t0s][1], ph[t0s][2], ph[t0s][3], vh0, vh1);
                MMA_BF16(o[j][0], o[j][1], o[j][2], o[j][3],
                         ph[t1s][0], ph[t1s][1], ph[t1s][2], ph[t1s][3], vh2, vh3);
                MMA_BF16(o[j][0], o[j][1], o[j][2], o[j][3],
                         ph[t0s][0], ph[t0s][1], ph[t0s][2], ph[t0s][3], vl0, vl1);
                MMA_BF16(o[j][0], o[j][1], o[j][2], o[j][3],
                         ph[t1s][0], ph[t1s][1], ph[t1s][2], ph[t1s][3], vl2, vl3);
                MMA_BF16(o[j][0], o[j][1], o[j][2], o[j][3],
                         pl[t0s][0], pl[t0s][1], pl[t0s][2], pl[t0s][3], vh0, vh1);
                MMA_BF16(o[j][0], o[j][1], o[j][2], o[j][3],
                         pl[t1s][0], pl[t1s][1], pl[t1s][2], pl[t1s][3], vh2, vh3);
            }
        }
        __syncthreads();
    }

    // --- normalize + store ---
    {
        float inv0 = 1.0f / l0, inv1 = 1.0f / l1;
        float* op = g_o + ((size_t)bh * TT + q0 + wrow) * DD;
#pragma unroll
        for (int j = 0; j < 8; j++) {
            int col = j * 8 + tg * 2;
            *reinterpret_cast<float2*>(op + (size_t)g * DD + col) =
                make_float2(o[j][0] * inv0, o[j][1] * inv0);
            *reinterpret_cast<float2*>(op + (size_t)(g + 8) * DD + col) =
                make_float2(o[j][2] * inv1, o[j][3] * inv1);
        }
    }
}

// ---------------------------------------------------------------------------
// Kernel 3: output projection. grid (TT/64, BB), block (16,16)
// ---------------------------------------------------------------------------
__global__ void proj_kernel(const float* __restrict__ W_proj,
                            const float* __restrict__ b_proj,
                            float* __restrict__ out) {
    __shared__ __align__(16) float a_s[64][65];
    __shared__ __align__(16) float w_s[64][64];

    const int b  = blockIdx.y;
    const int t0 = blockIdx.x * 64;
    const int tx = threadIdx.x, ty = threadIdx.y;
    const int tid = ty * 16 + tx;
    const int c0 = tx * 4;

    float acc[4][4] = {};
    for (int h = 0; h < HH; h++) {
        __syncthreads();
        const float* aptr = g_o + (((size_t)b * HH + h) * TT + t0) * DD;
        const float* wptr = W_proj + (size_t)h * DD * CC;
        for (int i = tid; i < 1024; i += 256) {
            int r = i >> 4, c4 = (i & 15) << 2;
            float4 v = reinterpret_cast<const float4*>(aptr)[i];
            a_s[r][c4] = v.x; a_s[r][c4+1] = v.y; a_s[r][c4+2] = v.z; a_s[r][c4+3] = v.w;
            *reinterpret_cast<float4*>(&w_s[r][c4]) = reinterpret_cast<const float4*>(wptr)[i];
        }
        __syncthreads();
#pragma unroll 8
        for (int d = 0; d < DD; d++) {
            float4 wv = *reinterpret_cast<const float4*>(&w_s[d][c0]);
#pragma unroll
            for (int i = 0; i < 4; i++) {
                float av = a_s[ty + 16 * i][d];
                acc[i][0] = fmaf(av, wv.x, acc[i][0]);
                acc[i][1] = fmaf(av, wv.y, acc[i][1]);
                acc[i][2] = fmaf(av, wv.z, acc[i][2]);
                acc[i][3] = fmaf(av, wv.w, acc[i][3]);
            }
        }
    }

    float bp0 = b_proj[c0], bp1 = b_proj[c0+1], bp2 = b_proj[c0+2], bp3 = b_proj[c0+3];
    float* optr = out + ((size_t)b * TT + t0) * CC;
#pragma unroll
    for (int i = 0; i < 4; i++) {
        float4 o4 = make_float4(acc[i][0] + bp0, acc[i][1] + bp1,
                                acc[i][2] + bp2, acc[i][3] + bp3);
        *reinterpret_cast<float4*>(optr + (size_t)(ty + 16 * i) * CC + c0) = o4;
    }
}

// ---------------------------------------------------------------------------
extern "C" void kernel_launch(void* const* d_in, const int* in_sizes, int n_in,
                              void* d_out, int out_size) {
    const float* x      = (const float*)d_in[0];
    const float* y      = (const float*)d_in[1];
    const float* Wq     = (const float*)d_in[2];
    const float* Wk     = (const float*)d_in[3];
    const float* Wv     = (const float*)d_in[4];
    const float* W_proj = (const float*)d_in[5];
    const float* b_proj = (const float*)d_in[6];
    float* out = (float*)d_out;
    (void)in_sizes; (void)n_in; (void)out_size;

    qkv_kernel<<<dim3(TT / 128, BH, 3), dim3(16, 16)>>>(x, y, Wq, Wk, Wv);
    attn_mma_kernel<<<dim3(TT / 64, BH), 128>>>();
    proj_kernel<<<dim3(TT / 64, BB), dim3(16, 16)>>>(W_proj, b_proj, out);
}

// round 5
// speedup vs baseline: 2.5181x; 1.0593x over previous
#include <cuda_runtime.h>
#include <cuda_bf16.h>
#include <cstdint>

#define BB 4
#define TT 2048
#define CC 64
#define HH 6
#define DD 64
#define BH (BB*HH)
#define NEG_BIG (-1e30f)

// ---------------------------------------------------------------------------
// Scratch (__device__ globals; allocation-free rule)
// ---------------------------------------------------------------------------
__device__ __nv_bfloat16 g_qhi[(size_t)BH*TT*DD];
__device__ __nv_bfloat16 g_qlo[(size_t)BH*TT*DD];
__device__ __nv_bfloat16 g_khi[(size_t)BH*TT*DD];
__device__ __nv_bfloat16 g_klo[(size_t)BH*TT*DD];
__device__ __nv_bfloat16 g_vthi[(size_t)BH*DD*TT];   // transposed: [bh][d][t]
__device__ __nv_bfloat16 g_vtlo[(size_t)BH*DD*TT];
__device__ float g_o[(size_t)BH*TT*DD];

__device__ __forceinline__ uint32_t smem_u32(const void* p) {
    uint32_t a;
    asm("{ .reg .u64 t; cvta.to.shared.u64 t, %1; cvt.u32.u64 %0, t; }"
        : "=r"(a) : "l"(p));
    return a;
}

#define LDMATRIX_X4(r0, r1, r2, r3, addr) \
    asm volatile("ldmatrix.sync.aligned.m8n8.x4.shared.b16 {%0,%1,%2,%3}, [%4];" \
        : "=r"(r0), "=r"(r1), "=r"(r2), "=r"(r3) : "r"(addr))

#define MMA_BF16(d0, d1, d2, d3, a0, a1, a2, a3, b0, b1) \
    asm volatile("mma.sync.aligned.m16n8k16.row.col.f32.bf16.bf16.f32 " \
        "{%0,%1,%2,%3}, {%4,%5,%6,%7}, {%8,%9}, {%0,%1,%2,%3};" \
        : "+f"(d0), "+f"(d1), "+f"(d2), "+f"(d3) \
        : "r"(a0), "r"(a1), "r"(a2), "r"(a3), "r"(b0), "r"(b1))

#define CP_ASYNC16(saddr, gaddr) \
    asm volatile("cp.async.cg.shared.global [%0], [%1], 16;" \
        :: "r"(saddr), "l"(gaddr) : "memory")
#define CP_COMMIT() asm volatile("cp.async.commit_group;" ::: "memory")
#define CP_WAIT0()  asm volatile("cp.async.wait_group 0;" ::: "memory")
#define CP_WAIT1()  asm volatile("cp.async.wait_group 1;" ::: "memory")

__device__ __forceinline__ uint32_t pack_bf16x2(__nv_bfloat16 a, __nv_bfloat16 b) {
    return (uint32_t)__bfloat16_as_ushort(a) | ((uint32_t)__bfloat16_as_ushort(b) << 16);
}
__device__ __forceinline__ void split_pack(float a, float b, uint32_t& hi, uint32_t& lo) {
    __nv_bfloat16 ah = __float2bfloat16(a);
    __nv_bfloat16 bh = __float2bfloat16(b);
    __nv_bfloat16 al = __float2bfloat16(a - __bfloat162float(ah));
    __nv_bfloat16 bl = __float2bfloat16(b - __bfloat162float(bh));
    hi = pack_bf16x2(ah, bh);
    lo = pack_bf16x2(al, bl);
}

// ---------------------------------------------------------------------------
// Kernel 1: QKV projection, 128 threads, 128-row x 64-col tile, 8x8 micro-tile.
// grid (TT/128, BH, 3). Dynamic smem: a_s[128*65] floats + w_s[64*64] floats.
// ---------------------------------------------------------------------------
#define QKV_SMEM ((128*65 + 64*64) * 4)

__global__ void __launch_bounds__(128) qkv_kernel(
        const float* __restrict__ x, const float* __restrict__ y,
        const float* __restrict__ Wq, const float* __restrict__ Wk,
        const float* __restrict__ Wv) {
    extern __shared__ __align__(16) float qsm[];
    float* a_s = qsm;             // [128][65]
    float* w_s = qsm + 128 * 65;  // [64][64]

    const int sel = blockIdx.z;
    const int bh  = blockIdx.y;
    const int b   = bh / HH, h = bh % HH;
    const int t0  = blockIdx.x * 128;

    const float* src = (sel == 0 ? x : y) + ((size_t)b * TT + t0) * CC;
    const float* W   = (sel == 0 ? Wq : (sel == 1 ? Wk : Wv)) + (size_t)h * CC * DD;

    const int tid  = threadIdx.x;
    const int colg = tid & 7;        // 8 col groups of 8
    const int rowg = tid >> 3;       // 16 row groups
    const int c0   = colg * 8;

    for (int i = tid; i < 2048; i += 128) {       // 128x64 as float4
        int r = i >> 4, c4 = (i & 15) << 2;
        float4 v = reinterpret_cast<const float4*>(src)[i];
        float* dst = a_s + r * 65 + c4;
        dst[0] = v.x; dst[1] = v.y; dst[2] = v.z; dst[3] = v.w;
    }
    for (int i = tid; i < 1024; i += 128) {       // 64x64 as float4
        reinterpret_cast<float4*>(w_s)[i] = reinterpret_cast<const float4*>(W)[i];
    }
    __syncthreads();

    float acc[8][8] = {};
#pragma unroll 4
    for (int c = 0; c < CC; c++) {
        float4 w0 = *reinterpret_cast<const float4*>(w_s + c * 64 + c0);
        float4 w1 = *reinterpret_cast<const float4*>(w_s + c * 64 + c0 + 4);
#pragma unroll
        for (int i = 0; i < 8; i++) {
            float av = a_s[(rowg + 16 * i) * 65 + c];
            acc[i][0] = fmaf(av, w0.x, acc[i][0]);
            acc[i][1] = fmaf(av, w0.y, acc[i][1]);
            acc[i][2] = fmaf(av, w0.z, acc[i][2]);
            acc[i][3] = fmaf(av, w0.w, acc[i][3]);
            acc[i][4] = fmaf(av, w1.x, acc[i][4]);
            acc[i][5] = fmaf(av, w1.y, acc[i][5]);
            acc[i][6] = fmaf(av, w1.z, acc[i][6]);
            acc[i][7] = fmaf(av, w1.w, acc[i][7]);
        }
    }

    if (sel < 2) {
        __nv_bfloat16* ghi = (sel == 0 ? g_qhi : g_khi);
        __nv_bfloat16* glo = (sel == 0 ? g_qlo : g_klo);
#pragma unroll
        for (int i = 0; i < 8; i++) {
            int t = t0 + rowg + 16 * i;
            size_t base = ((size_t)bh * TT + t) * DD + c0;
            uint32_t hv[4], lv[4];
#pragma unroll
            for (int p = 0; p < 4; p++)
                split_pack(acc[i][2 * p], acc[i][2 * p + 1], hv[p], lv[p]);
            *reinterpret_cast<uint4*>(ghi + base) = make_uint4(hv[0], hv[1], hv[2], hv[3]);
            *reinterpret_cast<uint4*>(glo + base) = make_uint4(lv[0], lv[1], lv[2], lv[3]);
        }
    } else {
        // V: transpose via smem staging (reuse a_s: [64 d][128 t] hi, +8192 lo)
        __syncthreads();
        __nv_bfloat16* vs = reinterpret_cast<__nv_bfloat16*>(a_s);
#pragma unroll
        for (int i = 0; i < 8; i++) {
            int key = rowg + 16 * i;
#pragma unroll
            for (int j = 0; j < 8; j++) {
                int d = c0 + j;
                float v = acc[i][j];
                __nv_bfloat16 hv = __float2bfloat16(v);
                __nv_bfloat16 lv = __float2bfloat16(v - __bfloat162float(hv));
                vs[d * 128 + key] = hv;
                vs[8192 + d * 128 + key] = lv;
            }
        }
        __syncthreads();
        for (int u = tid; u < 1024; u += 128) {
            int d = u >> 4, g = u & 15;
            uint4 hv = *reinterpret_cast<uint4*>(vs + d * 128 + g * 8);
            uint4 lv = *reinterpret_cast<uint4*>(vs + 8192 + d * 128 + g * 8);
            size_t dst = ((size_t)bh * DD + d) * TT + t0 + g * 8;
            *reinterpret_cast<uint4*>(g_vthi + dst) = hv;
            *reinterpret_cast<uint4*>(g_vtlo + dst) = lv;
        }
    }
}

// ---------------------------------------------------------------------------
// Kernel 2: causal flash attention via mma.sync (bf16 hi/lo, 3 chains).
// 128 q-rows per CTA, 8 warps, key tiles of 64, cp.async double buffer.
// grid 384 (1D, heavy qt first).
// ---------------------------------------------------------------------------
#define KSTRIDE 72                      // bf16 elems per smem row (144 B)
#define ARR_B   (64 * KSTRIDE * 2)      // 9216 B per array
#define STG_B   (4 * ARR_B)             // 36864 B per stage
#define ATTN_SMEM (2 * STG_B)           // 73728 B

__global__ void __launch_bounds__(256) attn_mma_kernel() {
    extern __shared__ __align__(16) char smem[];
    const uint32_t sbase = smem_u32(smem);

    const int tid  = threadIdx.x;
    const int wid  = tid >> 5, lane = tid & 31;
    const int g    = lane >> 2, tg = lane & 3;
    const int bid  = blockIdx.x;
    const int qt   = (TT / 128 - 1) - bid / BH;    // heavy tiles first
    const int bh   = bid % BH;
    const int q0   = qt * 128;
    const int wrow = wid * 16;
    const int njt  = 2 * qt + 2;

    const __nv_bfloat16* khB = g_khi + (size_t)bh * TT * DD;
    const __nv_bfloat16* klB = g_klo + (size_t)bh * TT * DD;
    const __nv_bfloat16* vhB = g_vthi + (size_t)bh * DD * TT;
    const __nv_bfloat16* vlB = g_vtlo + (size_t)bh * DD * TT;

    // --- stage key tile jt into buffer s (8 cp.async per thread) ---
    auto stage = [&](int s, int jt) {
        const int j0 = jt * 64;
        const uint32_t so = sbase + (uint32_t)s * STG_B;
#pragma unroll
        for (int u = tid; u < 512; u += 256) {
            int r = u >> 3, ch = (u & 7) * 8;
            uint32_t off = (uint32_t)(r * (KSTRIDE * 2) + ch * 2);
            CP_ASYNC16(so + off,              khB + (size_t)(j0 + r) * DD + ch);
            CP_ASYNC16(so + ARR_B + off,      klB + (size_t)(j0 + r) * DD + ch);
            CP_ASYNC16(so + 2 * ARR_B + off,  vhB + (size_t)r * TT + j0 + ch);
            CP_ASYNC16(so + 3 * ARR_B + off,  vlB + (size_t)r * TT + j0 + ch);
        }
    };

    // --- Q fragments (loaded once) ---
    uint32_t qh[4][4], ql[4][4];
    {
        const __nv_bfloat16* qbh = g_qhi + ((size_t)bh * TT + q0 + wrow) * DD;
        const __nv_bfloat16* qbl = g_qlo + ((size_t)bh * TT + q0 + wrow) * DD;
#pragma unroll
        for (int t = 0; t < 4; t++) {
            int col0 = t * 16 + tg * 2;
            qh[t][0] = *reinterpret_cast<const uint32_t*>(qbh + (size_t)g * DD + col0);
            qh[t][1] = *reinterpret_cast<const uint32_t*>(qbh + (size_t)(g + 8) * DD + col0);
            qh[t][2] = *reinterpret_cast<const uint32_t*>(qbh + (size_t)g * DD + col0 + 8);
            qh[t][3] = *reinterpret_cast<const uint32_t*>(qbh + (size_t)(g + 8) * DD + col0 + 8);
            ql[t][0] = *reinterpret_cast<const uint32_t*>(qbl + (size_t)g * DD + col0);
            ql[t][1] = *reinterpret_cast<const uint32_t*>(qbl + (size_t)(g + 8) * DD + col0);
            ql[t][2] = *reinterpret_cast<const uint32_t*>(qbl + (size_t)g * DD + col0 + 8);
            ql[t][3] = *reinterpret_cast<const uint32_t*>(qbl + (size_t)(g + 8) * DD + col0 + 8);
        }
    }

    float o[8][4];
#pragma unroll
    for (int j = 0; j < 8; j++)
#pragma unroll
        for (int e = 0; e < 4; e++) o[j][e] = 0.0f;
    float m0 = NEG_BIG, m1 = NEG_BIG, l0 = 0.0f, l1 = 0.0f;
    const int row0 = q0 + wrow + g, row1 = row0 + 8;
    const int rowmax = q0 + wrow + 15;
    const float scale = 0.125f;

    const int lrow = lane & 7;
    const int lmi  = lane >> 3;

    stage(0, 0);
    CP_COMMIT();

    for (int jt = 0; jt < njt; jt++) {
        const int j0 = jt * 64;
        if (jt + 1 < njt) {
            stage((jt + 1) & 1, jt + 1);
            CP_COMMIT();
            CP_WAIT1();
        } else {
            CP_WAIT0();
        }
        __syncthreads();

        if (j0 <= rowmax) {   // skip fully-masked key tiles for this warp
            const uint32_t so = sbase + (uint32_t)(jt & 1) * STG_B;
            const uint32_t skhi_b = so;
            const uint32_t sklo_b = so + ARR_B;
            const uint32_t svhi_b = so + 2 * ARR_B;
            const uint32_t svlo_b = so + 3 * ARR_B;

            // --- S = Q K^T (3 chains) ---
            float c[8][4];
#pragma unroll
            for (int j = 0; j < 8; j++)
#pragma unroll
                for (int e = 0; e < 4; e++) c[j][e] = 0.0f;

#pragma unroll
            for (int j = 0; j < 8; j++) {
                uint32_t roff = (uint32_t)((j * 8 + lrow) * KSTRIDE + lmi * 8) * 2;
#pragma unroll
                for (int tp = 0; tp < 2; tp++) {
                    uint32_t coff = roff + (uint32_t)(tp * 64);
                    uint32_t kh0, kh1, kh2, kh3, kl0, kl1, kl2, kl3;
                    LDMATRIX_X4(kh0, kh1, kh2, kh3, skhi_b + coff);
                    LDMATRIX_X4(kl0, kl1, kl2, kl3, sklo_b + coff);
                    int t0s = 2 * tp, t1s = 2 * tp + 1;
                    MMA_BF16(c[j][0], c[j][1], c[j][2], c[j][3],
                             qh[t0s][0], qh[t0s][1], qh[t0s][2], qh[t0s][3], kh0, kh1);
                    MMA_BF16(c[j][0], c[j][1], c[j][2], c[j][3],
                             qh[t1s][0], qh[t1s][1], qh[t1s][2], qh[t1s][3], kh2, kh3);
                    MMA_BF16(c[j][0], c[j][1], c[j][2], c[j][3],
                             qh[t0s][0], qh[t0s][1], qh[t0s][2], qh[t0s][3], kl0, kl1);
                    MMA_BF16(c[j][0], c[j][1], c[j][2], c[j][3],
                             qh[t1s][0], qh[t1s][1], qh[t1s][2], qh[t1s][3], kl2, kl3);
                    MMA_BF16(c[j][0], c[j][1], c[j][2], c[j][3],
                             ql[t0s][0], ql[t0s][1], ql[t0s][2], ql[t0s][3], kh0, kh1);
                    MMA_BF16(c[j][0], c[j][1], c[j][2], c[j][3],
                             ql[t1s][0], ql[t1s][1], ql[t1s][2], ql[t1s][3], kh2, kh3);
                }
            }

            // --- softmax ---
            const bool m0p = (j0 + 63 > row0);
            const bool m1p = (j0 + 63 > row1);
            float mx0 = NEG_BIG, mx1 = NEG_BIG;
#pragma unroll
            for (int j = 0; j < 8; j++) {
#pragma unroll
                for (int e = 0; e < 2; e++) {
                    int col = j0 + j * 8 + tg * 2 + e;
                    float v0 = c[j][e] * scale;
                    float v1 = c[j][2 + e] * scale;
                    if (m0p && col > row0) v0 = NEG_BIG;
                    if (m1p && col > row1) v1 = NEG_BIG;
                    c[j][e] = v0; c[j][2 + e] = v1;
                    mx0 = fmaxf(mx0, v0); mx1 = fmaxf(mx1, v1);
                }
            }
            mx0 = fmaxf(mx0, __shfl_xor_sync(0xffffffffu, mx0, 1));
            mx0 = fmaxf(mx0, __shfl_xor_sync(0xffffffffu, mx0, 2));
            mx1 = fmaxf(mx1, __shfl_xor_sync(0xffffffffu, mx1, 1));
            mx1 = fmaxf(mx1, __shfl_xor_sync(0xffffffffu, mx1, 2));

            float mn0 = fmaxf(m0, mx0), mn1 = fmaxf(m1, mx1);
            float corr0 = __expf(m0 - mn0), corr1 = __expf(m1 - mn1);
            m0 = mn0; m1 = mn1;

            float s0 = 0.0f, s1 = 0.0f;
#pragma unroll
            for (int j = 0; j < 8; j++) {
#pragma unroll
                for (int e = 0; e < 2; e++) {
                    float p0 = __expf(c[j][e] - mn0);
                    float p1 = __expf(c[j][2 + e] - mn1);
                    c[j][e] = p0; c[j][2 + e] = p1;
                    s0 += p0; s1 += p1;
                }
            }
            s0 += __shfl_xor_sync(0xffffffffu, s0, 1);
            s0 += __shfl_xor_sync(0xffffffffu, s0, 2);
            s1 += __shfl_xor_sync(0xffffffffu, s1, 1);
            s1 += __shfl_xor_sync(0xffffffffu, s1, 2);
            l0 = l0 * corr0 + s0;
            l1 = l1 * corr1 + s1;

#pragma unroll
            for (int j = 0; j < 8; j++) {
                o[j][0] *= corr0; o[j][1] *= corr0;
                o[j][2] *= corr1; o[j][3] *= corr1;
            }

            // --- P fragments from S accumulators ---
            uint32_t ph[4][4], pl[4][4];
#pragma unroll
            for (int t = 0; t < 4; t++) {
                split_pack(c[2 * t][0],     c[2 * t][1],     ph[t][0], pl[t][0]);
                split_pack(c[2 * t][2],     c[2 * t][3],     ph[t][1], pl[t][1]);
                split_pack(c[2 * t + 1][0], c[2 * t + 1][1], ph[t][2], pl[t][2]);
                split_pack(c[2 * t + 1][2], c[2 * t + 1][3], ph[t][3], pl[t][3]);
            }

            // --- O += P V (3 chains) ---
#pragma unroll
            for (int j = 0; j < 8; j++) {
                uint32_t roff = (uint32_t)((j * 8 + lrow) * KSTRIDE + lmi * 8) * 2;
#pragma unroll
                for (int tp = 0; tp < 2; tp++) {
                    uint32_t coff = roff + (uint32_t)(tp * 64);
                    uint32_t vh0, vh1, vh2, vh3, vl0, vl1, vl2, vl3;
                    LDMATRIX_X4(vh0, vh1, vh2, vh3, svhi_b + coff);
                    LDMATRIX_X4(vl0, vl1, vl2, vl3, svlo_b + coff);
                    int t0s = 2 * tp, t1s = 2 * tp + 1;
                    MMA_BF16(o[j][0], o[j][1], o[j][2], o[j][3],
                             ph[t0s][0], ph[t0s][1], ph[t0s][2], ph[t0s][3], vh0, vh1);
                    MMA_BF16(o[j][0], o[j][1], o[j][2], o[j][3],
                             ph[t1s][0], ph[t1s][1], ph[t1s][2], ph[t1s][3], vh2, vh3);
                    MMA_BF16(o[j][0], o[j][1], o[j][2], o[j][3],
                             ph[t0s][0], ph[t0s][1], ph[t0s][2], ph[t0s][3], vl0, vl1);
                    MMA_BF16(o[j][0], o[j][1], o[j][2], o[j][3],
                             ph[t1s][0], ph[t1s][1], ph[t1s][2], ph[t1s][3], vl2, vl3);
                    MMA_BF16(o[j][0], o[j][1], o[j][2], o[j][3],
                             pl[t0s][0], pl[t0s][1], pl[t0s][2], pl[t0s][3], vh0, vh1);
                    MMA_BF16(o[j][0], o[j][1], o[j][2], o[j][3],
                             pl[t1s][0], pl[t1s][1], pl[t1s][2], pl[t1s][3], vh2, vh3);
                }
            }
        }
        __syncthreads();
    }

    // --- normalize + store ---
    {
        float inv0 = 1.0f / l0, inv1 = 1.0f / l1;
        float* op = g_o + ((size_t)bh * TT + q0 + wrow) * DD;
#pragma unroll
        for (int j = 0; j < 8; j++) {
            int col = j * 8 + tg * 2;
            *reinterpret_cast<float2*>(op + (size_t)g * DD + col) =
                make_float2(o[j][0] * inv0, o[j][1] * inv0);
            *reinterpret_cast<float2*>(op + (size_t)(g + 8) * DD + col) =
                make_float2(o[j][2] * inv1, o[j][3] * inv1);
        }
    }
}

// ---------------------------------------------------------------------------
// Kernel 3: output projection, 128 threads, 128-row tile, 8x8 micro-tile.
// grid (TT/128, BB).
// ---------------------------------------------------------------------------
#define PROJ_SMEM ((128*65 + 64*64) * 4)

__global__ void __launch_bounds__(128) proj_kernel(
        const float* __restrict__ W_proj, const float* __restrict__ b_proj,
        float* __restrict__ out) {
    extern __shared__ __align__(16) float psm[];
    float* a_s = psm;             // [128][65]
    float* w_s = psm + 128 * 65;  // [64][64]

    const int b  = blockIdx.y;
    const int t0 = blockIdx.x * 128;
    const int tid  = threadIdx.x;
    const int colg = tid & 7;
    const int rowg = tid >> 3;
    const int c0   = colg * 8;

    float acc[8][8] = {};
    for (int h = 0; h < HH; h++) {
        __syncthreads();
        const float* aptr = g_o + (((size_t)b * HH + h) * TT + t0) * DD;
        const float* wptr = W_proj + (size_t)h * DD * CC;
        for (int i = tid; i < 2048; i += 128) {
            int r = i >> 4, c4 = (i & 15) << 2;
            float4 v = reinterpret_cast<const float4*>(aptr)[i];
            float* dst = a_s + r * 65 + c4;
            dst[0] = v.x; dst[1] = v.y; dst[2] = v.z; dst[3] = v.w;
        }
        for (int i = tid; i < 1024; i += 128)
            reinterpret_cast<float4*>(w_s)[i] = reinterpret_cast<const float4*>(wptr)[i];
        __syncthreads();
#pragma unroll 4
        for (int d = 0; d < DD; d++) {
            float4 w0 = *reinterpret_cast<const float4*>(w_s + d * 64 + c0);
            float4 w1 = *reinterpret_cast<const float4*>(w_s + d * 64 + c0 + 4);
#pragma unroll
            for (int i = 0; i < 8; i++) {
                float av = a_s[(rowg + 16 * i) * 65 + d];
                acc[i][0] = fmaf(av, w0.x, acc[i][0]);
                acc[i][1] = fmaf(av, w0.y, acc[i][1]);
                acc[i][2] = fmaf(av, w0.z, acc[i][2]);
                acc[i][3] = fmaf(av, w0.w, acc[i][3]);
                acc[i][4] = fmaf(av, w1.x, acc[i][4]);
                acc[i][5] = fmaf(av, w1.y, acc[i][5]);
                acc[i][6] = fmaf(av, w1.z, acc[i][6]);
                acc[i][7] = fmaf(av, w1.w, acc[i][7]);
            }
        }
    }

    float bp[8];
#pragma unroll
    for (int j = 0; j < 8; j++) bp[j] = b_proj[c0 + j];

    float* optr = out + ((size_t)b * TT + t0) * CC;
#pragma unroll
    for (int i = 0; i < 8; i++) {
        float4 o0 = make_float4(acc[i][0] + bp[0], acc[i][1] + bp[1],
                                acc[i][2] + bp[2], acc[i][3] + bp[3]);
        float4 o1 = make_float4(acc[i][4] + bp[4], acc[i][5] + bp[5],
                                acc[i][6] + bp[6], acc[i][7] + bp[7]);
        float* dst = optr + (size_t)(rowg + 16 * i) * CC + c0;
        *reinterpret_cast<float4*>(dst)     = o0;
        *reinterpret_cast<float4*>(dst + 4) = o1;
    }
}

// ---------------------------------------------------------------------------
extern "C" void kernel_launch(void* const* d_in, const int* in_sizes, int n_in,
                              void* d_out, int out_size) {
    const float* x      = (const float*)d_in[0];
    const float* y      = (const float*)d_in[1];
    const float* Wq     = (const float*)d_in[2];
    const float* Wk     = (const float*)d_in[3];
    const float* Wv     = (const float*)d_in[4];
    const float* W_proj = (const float*)d_in[5];
    const float* b_proj = (const float*)d_in[6];
    float* out = (float*)d_out;
    (void)in_sizes; (void)n_in; (void)out_size;

    static int inited = 0;
    if (!inited) {
        cudaFuncSetAttribute(qkv_kernel,
                             cudaFuncAttributeMaxDynamicSharedMemorySize, QKV_SMEM);
        cudaFuncSetAttribute(attn_mma_kernel,
                             cudaFuncAttributeMaxDynamicSharedMemorySize, ATTN_SMEM);
        cudaFuncSetAttribute(proj_kernel,
                             cudaFuncAttributeMaxDynamicSharedMemorySize, PROJ_SMEM);
        inited = 1;
    }

    qkv_kernel<<<dim3(TT / 128, BH, 3), 128, QKV_SMEM>>>(x, y, Wq, Wk, Wv);
    attn_mma_kernel<<<(TT / 128) * BH, 256, ATTN_SMEM>>>();
    proj_kernel<<<dim3(TT / 128, BB), 128, PROJ_SMEM>>>(W_proj, b_proj, out);
}

// round 6
// speedup vs baseline: 3.6685x; 1.4568x over previous
#include <cuda_runtime.h>
#include <cuda_fp16.h>
#include <cstdint>

#define BB 4
#define TT 2048
#define CC 64
#define HH 6
#define DD 64
#define BH (BB*HH)
#define NEG_BIG (-1e30f)

// ---------------------------------------------------------------------------
// Scratch (__device__ globals; allocation-free rule). fp16 hi/lo splits.
// ---------------------------------------------------------------------------
__device__ __half g_qh [(size_t)BH*TT*DD];
__device__ __half g_kh [(size_t)BH*TT*DD];
__device__ __half g_kl [(size_t)BH*TT*DD];
__device__ __half g_vth[(size_t)BH*DD*TT];   // transposed: [bh][d][t]
__device__ __half g_vtl[(size_t)BH*DD*TT];
__device__ float  g_o  [(size_t)BH*TT*DD];

__device__ __forceinline__ uint32_t smem_u32(const void* p) {
    uint32_t a;
    asm("{ .reg .u64 t; cvta.to.shared.u64 t, %1; cvt.u32.u64 %0, t; }"
        : "=r"(a) : "l"(p));
    return a;
}

#define LDMATRIX_X4(r0, r1, r2, r3, addr) \
    asm volatile("ldmatrix.sync.aligned.m8n8.x4.shared.b16 {%0,%1,%2,%3}, [%4];" \
        : "=r"(r0), "=r"(r1), "=r"(r2), "=r"(r3) : "r"(addr))

#define MMA_F16(d0, d1, d2, d3, a0, a1, a2, a3, b0, b1) \
    asm volatile("mma.sync.aligned.m16n8k16.row.col.f32.f16.f16.f32 " \
        "{%0,%1,%2,%3}, {%4,%5,%6,%7}, {%8,%9}, {%0,%1,%2,%3};" \
        : "+f"(d0), "+f"(d1), "+f"(d2), "+f"(d3) \
        : "r"(a0), "r"(a1), "r"(a2), "r"(a3), "r"(b0), "r"(b1))

#define CP_ASYNC16(saddr, gaddr) \
    asm volatile("cp.async.cg.shared.global [%0], [%1], 16;" \
        :: "r"(saddr), "l"(gaddr) : "memory")
#define CP_COMMIT() asm volatile("cp.async.commit_group;" ::: "memory")
#define CP_WAIT0()  asm volatile("cp.async.wait_group 0;" ::: "memory")
#define CP_WAIT1()  asm volatile("cp.async.wait_group 1;" ::: "memory")

__device__ __forceinline__ uint32_t pack_h2(__half a, __half b) {
    return (uint32_t)__half_as_ushort(a) | ((uint32_t)__half_as_ushort(b) << 16);
}
__device__ __forceinline__ void split_h(float v, __half& hi, __half& lo) {
    hi = __float2half_rn(v);
    lo = __float2half_rn(v - __half2float(hi));
}

// ---------------------------------------------------------------------------
// Kernel 1: QKV projection via mma.sync (fp16 hi/lo, 3 chains).
// grid (TT/128, BH, 3), block 128 (4 warps x 32 rows).
// smem: xh[128*72], xl[128*72], wTh[64*72], wTl[64*72] halves = 55296 B
// ---------------------------------------------------------------------------
#define XS 72
#define QKV_SMEM ((2*128*XS + 2*64*XS) * 2)

__global__ void __launch_bounds__(128) qkv_kernel(
        const float* __restrict__ x, const float* __restrict__ y,
        const float* __restrict__ Wq, const float* __restrict__ Wk,
        const float* __restrict__ Wv) {
    extern __shared__ __align__(16) __half qsm[];
    __half* xh  = qsm;
    __half* xl  = xh + 128 * XS;
    __half* wTh = xl + 128 * XS;
    __half* wTl = wTh + 64 * XS;

    const int sel = blockIdx.z;
    const int bh  = blockIdx.y;
    const int b   = bh / HH, h = bh % HH;
    const int t0  = blockIdx.x * 128;

    const float* src = (sel == 0 ? x : y) + ((size_t)b * TT + t0) * CC;
    const float* W   = (sel == 0 ? Wq : (sel == 1 ? Wk : Wv)) + (size_t)h * CC * DD;

    const int tid  = threadIdx.x;
    const int wid  = tid >> 5, lane = tid & 31;
    const int g    = lane >> 2, tg = lane & 3;
    const int wrow = wid * 32;
    const int lrow = lane & 7;
    const int l8   = (lane >> 3) & 1;
    const int l16  = lane >> 4;

    // load + split x tile [128 x 64]
    for (int i = tid; i < 2048; i += 128) {
        int r = i >> 4, c4 = (i & 15) << 2;
        float4 v = reinterpret_cast<const float4*>(src)[i];
        __half h0, h1, h2, h3, l0, l1, l2, l3;
        split_h(v.x, h0, l0); split_h(v.y, h1, l1);
        split_h(v.z, h2, l2); split_h(v.w, h3, l3);
        *reinterpret_cast<uint2*>(xh + r * XS + c4) =
            make_uint2(pack_h2(h0, h1), pack_h2(h2, h3));
        *reinterpret_cast<uint2*>(xl + r * XS + c4) =
            make_uint2(pack_h2(l0, l1), pack_h2(l2, l3));
    }
    // load + split W transposed: wT[d][c] = W[c][d]
    for (int i = tid; i < 1024; i += 128) {
        int c = i >> 4, d4 = (i & 15) << 2;
        float4 v = reinterpret_cast<const float4*>(W)[i];
        __half hh, ll;
        split_h(v.x, hh, ll); wTh[(d4 + 0) * XS + c] = hh; wTl[(d4 + 0) * XS + c] = ll;
        split_h(v.y, hh, ll); wTh[(d4 + 1) * XS + c] = hh; wTl[(d4 + 1) * XS + c] = ll;
        split_h(v.z, hh, ll); wTh[(d4 + 2) * XS + c] = hh; wTl[(d4 + 2) * XS + c] = ll;
        split_h(v.w, hh, ll); wTh[(d4 + 3) * XS + c] = hh; wTl[(d4 + 3) * XS + c] = ll;
    }
    __syncthreads();

    const uint32_t xh_b  = smem_u32(xh);
    const uint32_t xl_b  = smem_u32(xl);
    const uint32_t wTh_b = smem_u32(wTh);
    const uint32_t wTl_b = smem_u32(wTl);

    float acc[2][8][4] = {};

#pragma unroll
    for (int kw = 0; kw < 2; kw++) {          // two k32 windows
        const int ck = kw * 32;
        uint32_t ah[2][2][4], al[2][2][4];    // [m][k16][reg]
#pragma unroll
        for (int m = 0; m < 2; m++)
#pragma unroll
            for (int kk = 0; kk < 2; kk++) {
                uint32_t off = (uint32_t)((wrow + m * 16 + lrow + l8 * 8) * XS
                                          + ck + kk * 16 + l16 * 8) * 2;
                LDMATRIX_X4(ah[m][kk][0], ah[m][kk][1], ah[m][kk][2], ah[m][kk][3],
                            xh_b + off);
                LDMATRIX_X4(al[m][kk][0], al[m][kk][1], al[m][kk][2], al[m][kk][3],
                            xl_b + off);
            }
#pragma unroll
        for (int j = 0; j < 8; j++) {
            uint32_t boff = (uint32_t)((j * 8 + lrow) * XS + ck + (lane >> 3) * 8) * 2;
            uint32_t bh0, bh1, bh2, bh3, bl0, bl1, bl2, bl3;
            LDMATRIX_X4(bh0, bh1, bh2, bh3, wTh_b + boff);
            LDMATRIX_X4(bl0, bl1, bl2, bl3, wTl_b + boff);
#pragma unroll
            for (int m = 0; m < 2; m++) {
                MMA_F16(acc[m][j][0], acc[m][j][1], acc[m][j][2], acc[m][j][3],
                        ah[m][0][0], ah[m][0][1], ah[m][0][2], ah[m][0][3], bh0, bh1);
                MMA_F16(acc[m][j][0], acc[m][j][1], acc[m][j][2], acc[m][j][3],
                        ah[m][1][0], ah[m][1][1], ah[m][1][2], ah[m][1][3], bh2, bh3);
                MMA_F16(acc[m][j][0], acc[m][j][1], acc[m][j][2], acc[m][j][3],
                        ah[m][0][0], ah[m][0][1], ah[m][0][2], ah[m][0][3], bl0, bl1);
                MMA_F16(acc[m][j][0], acc[m][j][1], acc[m][j][2], acc[m][j][3],
                        ah[m][1][0], ah[m][1][1], ah[m][1][2], ah[m][1][3], bl2, bl3);
                MMA_F16(acc[m][j][0], acc[m][j][1], acc[m][j][2], acc[m][j][3],
                        al[m][0][0], al[m][0][1], al[m][0][2], al[m][0][3], bh0, bh1);
                MMA_F16(acc[m][j][0], acc[m][j][1], acc[m][j][2], acc[m][j][3],
                        al[m][1][0], al[m][1][1], al[m][1][2], al[m][1][3], bh2, bh3);
            }
        }
    }

    if (sel == 0) {
        // Q: store hi only
#pragma unroll
        for (int m = 0; m < 2; m++)
#pragma unroll
            for (int j = 0; j < 8; j++) {
                int r0 = t0 + wrow + m * 16 + g;
                int col = j * 8 + tg * 2;
                *reinterpret_cast<uint32_t*>(g_qh + ((size_t)bh * TT + r0) * DD + col) =
                    pack_h2(__float2half_rn(acc[m][j][0]), __float2half_rn(acc[m][j][1]));
                *reinterpret_cast<uint32_t*>(g_qh + ((size_t)bh * TT + r0 + 8) * DD + col) =
                    pack_h2(__float2half_rn(acc[m][j][2]), __float2half_rn(acc[m][j][3]));
            }
    } else if (sel == 1) {
        // K: store hi + lo
#pragma unroll
        for (int m = 0; m < 2; m++)
#pragma unroll
            for (int j = 0; j < 8; j++) {
                int r0 = t0 + wrow + m * 16 + g;
                int col = j * 8 + tg * 2;
                __half h0, h1, h2, h3, l0, l1, l2, l3;
                split_h(acc[m][j][0], h0, l0); split_h(acc[m][j][1], h1, l1);
                split_h(acc[m][j][2], h2, l2); split_h(acc[m][j][3], h3, l3);
                size_t ba = ((size_t)bh * TT + r0) * DD + col;
                size_t bb = ((size_t)bh * TT + r0 + 8) * DD + col;
                *reinterpret_cast<uint32_t*>(g_kh + ba) = pack_h2(h0, h1);
                *reinterpret_cast<uint32_t*>(g_kh + bb) = pack_h2(h2, h3);
                *reinterpret_cast<uint32_t*>(g_kl + ba) = pack_h2(l0, l1);
                *reinterpret_cast<uint32_t*>(g_kl + bb) = pack_h2(l2, l3);
            }
    } else {
        // V: transpose via smem staging (reuse xh/xl as [64 d][136 t])
        __syncthreads();
        __half* vsh = xh;
        __half* vsl = xl;
#pragma unroll
        for (int m = 0; m < 2; m++)
#pragma unroll
            for (int j = 0; j < 8; j++) {
                int tA = wrow + m * 16 + g;
                int tBr = tA + 8;
                int d0 = j * 8 + tg * 2;
                __half hh, ll;
                split_h(acc[m][j][0], hh, ll);
                vsh[(d0)     * 136 + tA]  = hh; vsl[(d0)     * 136 + tA]  = ll;
                split_h(acc[m][j][1], hh, ll);
                vsh[(d0 + 1) * 136 + tA]  = hh; vsl[(d0 + 1) * 136 + tA]  = ll;
                split_h(acc[m][j][2], hh, ll);
                vsh[(d0)     * 136 + tBr] = hh; vsl[(d0)     * 136 + tBr] = ll;
                split_h(acc[m][j][3], hh, ll);
                vsh[(d0 + 1) * 136 + tBr] = hh; vsl[(d0 + 1) * 136 + tBr] = ll;
            }
        __syncthreads();
        for (int u = tid; u < 1024; u += 128) {
            int d = u >> 4, tc = (u & 15) * 8;
            uint4 hv = *reinterpret_cast<uint4*>(vsh + d * 136 + tc);
            uint4 lv = *reinterpret_cast<uint4*>(vsl + d * 136 + tc);
            size_t dst = ((size_t)bh * DD + d) * TT + t0 + tc;
            *reinterpret_cast<uint4*>(g_vth + dst) = hv;
            *reinterpret_cast<uint4*>(g_vtl + dst) = lv;
        }
    }
}

// ---------------------------------------------------------------------------
// Kernel 2: causal flash attention via mma.sync (fp16, 2 chains).
// 128 q-rows per CTA, 8 warps, key tiles of 64, cp.async double buffer.
// ---------------------------------------------------------------------------
#define KSTRIDE 72                      // fp16 elems per smem row (144 B)
#define ARR_B   (64 * KSTRIDE * 2)      // 9216 B per array
#define STG_B   (4 * ARR_B)             // 36864 B per stage
#define ATTN_SMEM (2 * STG_B)           // 73728 B

__global__ void __launch_bounds__(256) attn_mma_kernel() {
    extern __shared__ __align__(16) char smem[];
    const uint32_t sbase = smem_u32(smem);

    const int tid  = threadIdx.x;
    const int wid  = tid >> 5, lane = tid & 31;
    const int g    = lane >> 2, tg = lane & 3;
    const int bid  = blockIdx.x;
    const int qt   = (TT / 128 - 1) - bid / BH;    // heavy tiles first
    const int bh   = bid % BH;
    const int q0   = qt * 128;
    const int wrow = wid * 16;
    const int njt  = 2 * qt + 2;

    const __half* khB = g_kh + (size_t)bh * TT * DD;
    const __half* klB = g_kl + (size_t)bh * TT * DD;
    const __half* vhB = g_vth + (size_t)bh * DD * TT;
    const __half* vlB = g_vtl + (size_t)bh * DD * TT;

    auto stage = [&](int s, int jt) {
        const int j0 = jt * 64;
        const uint32_t so = sbase + (uint32_t)s * STG_B;
#pragma unroll
        for (int u = tid; u < 512; u += 256) {
            int r = u >> 3, ch = (u & 7) * 8;
            uint32_t off = (uint32_t)(r * (KSTRIDE * 2) + ch * 2);
            CP_ASYNC16(so + off,              khB + (size_t)(j0 + r) * DD + ch);
            CP_ASYNC16(so + ARR_B + off,      klB + (size_t)(j0 + r) * DD + ch);
            CP_ASYNC16(so + 2 * ARR_B + off,  vhB + (size_t)r * TT + j0 + ch);
            CP_ASYNC16(so + 3 * ARR_B + off,  vlB + (size_t)r * TT + j0 + ch);
        }
    };

    // --- Q fragments (hi only, loaded once) ---
    uint32_t qh[4][4];
    {
        const __half* qb = g_qh + ((size_t)bh * TT + q0 + wrow) * DD;
#pragma unroll
        for (int t = 0; t < 4; t++) {
            int col0 = t * 16 + tg * 2;
            qh[t][0] = *reinterpret_cast<const uint32_t*>(qb + (size_t)g * DD + col0);
            qh[t][1] = *reinterpret_cast<const uint32_t*>(qb + (size_t)(g + 8) * DD + col0);
            qh[t][2] = *reinterpret_cast<const uint32_t*>(qb + (size_t)g * DD + col0 + 8);
            qh[t][3] = *reinterpret_cast<const uint32_t*>(qb + (size_t)(g + 8) * DD + col0 + 8);
        }
    }

    float o[8][4];
#pragma unroll
    for (int j = 0; j < 8; j++)
#pragma unroll
        for (int e = 0; e < 4; e++) o[j][e] = 0.0f;
    float m0 = NEG_BIG, m1 = NEG_BIG, l0 = 0.0f, l1 = 0.0f;
    const int row0 = q0 + wrow + g, row1 = row0 + 8;
    const int rowmax = q0 + wrow + 15;
    const float scale = 0.125f;

    const int lrow = lane & 7;
    const int lmi  = lane >> 3;

    stage(0, 0);
    CP_COMMIT();

    for (int jt = 0; jt < njt; jt++) {
        const int j0 = jt * 64;
        if (jt + 1 < njt) {
            stage((jt + 1) & 1, jt + 1);
            CP_COMMIT();
            CP_WAIT1();
        } else {
            CP_WAIT0();
        }
        __syncthreads();

        if (j0 <= rowmax) {
            const uint32_t so = sbase + (uint32_t)(jt & 1) * STG_B;
            const uint32_t skh_b = so;
            const uint32_t skl_b = so + ARR_B;
            const uint32_t svh_b = so + 2 * ARR_B;
            const uint32_t svl_b = so + 3 * ARR_B;

            // --- S = Q K^T (2 chains: qh*kh + qh*kl) ---
            float c[8][4];
#pragma unroll
            for (int j = 0; j < 8; j++)
#pragma unroll
                for (int e = 0; e < 4; e++) c[j][e] = 0.0f;

#pragma unroll
            for (int j = 0; j < 8; j++) {
                uint32_t roff = (uint32_t)((j * 8 + lrow) * KSTRIDE + lmi * 8) * 2;
#pragma unroll
                for (int tp = 0; tp < 2; tp++) {
                    uint32_t coff = roff + (uint32_t)(tp * 64);
                    uint32_t kh0, kh1, kh2, kh3, kl0, kl1, kl2, kl3;
                    LDMATRIX_X4(kh0, kh1, kh2, kh3, skh_b + coff);
                    LDMATRIX_X4(kl0, kl1, kl2, kl3, skl_b + coff);
                    int t0s = 2 * tp, t1s = 2 * tp + 1;
                    MMA_F16(c[j][0], c[j][1], c[j][2], c[j][3],
                            qh[t0s][0], qh[t0s][1], qh[t0s][2], qh[t0s][3], kh0, kh1);
                    MMA_F16(c[j][0], c[j][1], c[j][2], c[j][3],
                            qh[t1s][0], qh[t1s][1], qh[t1s][2], qh[t1s][3], kh2, kh3);
                    MMA_F16(c[j][0], c[j][1], c[j][2], c[j][3],
                            qh[t0s][0], qh[t0s][1], qh[t0s][2], qh[t0s][3], kl0, kl1);
                    MMA_F16(c[j][0], c[j][1], c[j][2], c[j][3],
                            qh[t1s][0], qh[t1s][1], qh[t1s][2], qh[t1s][3], kl2, kl3);
                }
            }

            // --- softmax ---
            const bool m0p = (j0 + 63 > row0);
            const bool m1p = (j0 + 63 > row1);
            float mx0 = NEG_BIG, mx1 = NEG_BIG;
#pragma unroll
            for (int j = 0; j < 8; j++) {
#pragma unroll
                for (int e = 0; e < 2; e++) {
                    int col = j0 + j * 8 + tg * 2 + e;
                    float v0 = c[j][e] * scale;
                    float v1 = c[j][2 + e] * scale;
                    if (m0p && col > row0) v0 = NEG_BIG;
                    if (m1p && col > row1) v1 = NEG_BIG;
                    c[j][e] = v0; c[j][2 + e] = v1;
                    mx0 = fmaxf(mx0, v0); mx1 = fmaxf(mx1, v1);
                }
            }
            mx0 = fmaxf(mx0, __shfl_xor_sync(0xffffffffu, mx0, 1));
            mx0 = fmaxf(mx0, __shfl_xor_sync(0xffffffffu, mx0, 2));
            mx1 = fmaxf(mx1, __shfl_xor_sync(0xffffffffu, mx1, 1));
            mx1 = fmaxf(mx1, __shfl_xor_sync(0xffffffffu, mx1, 2));

            float mn0 = fmaxf(m0, mx0), mn1 = fmaxf(m1, mx1);
            float corr0 = __expf(m0 - mn0), corr1 = __expf(m1 - mn1);
            m0 = mn0; m1 = mn1;

            float s0 = 0.0f, s1 = 0.0f;
#pragma unroll
            for (int j = 0; j < 8; j++) {
#pragma unroll
                for (int e = 0; e < 2; e++) {
                    float p0 = __expf(c[j][e] - mn0);
                    float p1 = __expf(c[j][2 + e] - mn1);
                    c[j][e] = p0; c[j][2 + e] = p1;
                    s0 += p0; s1 += p1;
                }
            }
            s0 += __shfl_xor_sync(0xffffffffu, s0, 1);
            s0 += __shfl_xor_sync(0xffffffffu, s0, 2);
            s1 += __shfl_xor_sync(0xffffffffu, s1, 1);
            s1 += __shfl_xor_sync(0xffffffffu, s1, 2);
            l0 = l0 * corr0 + s0;
            l1 = l1 * corr1 + s1;

#pragma unroll
            for (int j = 0; j < 8; j++) {
                o[j][0] *= corr0; o[j][1] *= corr0;
                o[j][2] *= corr1; o[j][3] *= corr1;
            }

            // --- P fragments (hi only) ---
            uint32_t ph[4][4];
#pragma unroll
            for (int t = 0; t < 4; t++) {
                ph[t][0] = pack_h2(__float2half_rn(c[2*t][0]),   __float2half_rn(c[2*t][1]));
                ph[t][1] = pack_h2(__float2half_rn(c[2*t][2]),   __float2half_rn(c[2*t][3]));
                ph[t][2] = pack_h2(__float2half_rn(c[2*t+1][0]), __float2half_rn(c[2*t+1][1]));
                ph[t][3] = pack_h2(__float2half_rn(c[2*t+1][2]), __float2half_rn(c[2*t+1][3]));
            }

            // --- O += P V (2 chains: ph*vh + ph*vl) ---
#pragma unroll
            for (int j = 0; j < 8; j++) {
                uint32_t roff = (uint32_t)((j * 8 + lrow) * KSTRIDE + lmi * 8) * 2;
#pragma unroll
                for (int tp = 0; tp < 2; tp++) {
                    uint32_t coff = roff + (uint32_t)(tp * 64);
                    uint32_t vh0, vh1, vh2, vh3, vl0, vl1, vl2, vl3;
                    LDMATRIX_X4(vh0, vh1, vh2, vh3, svh_b + coff);
                    LDMATRIX_X4(vl0, vl1, vl2, vl3, svl_b + coff);
                    int t0s = 2 * tp, t1s = 2 * tp + 1;
                    MMA_F16(o[j][0], o[j][1], o[j][2], o[j][3],
                            ph[t0s][0], ph[t0s][1], ph[t0s][2], ph[t0s][3], vh0, vh1);
                    MMA_F16(o[j][0], o[j][1], o[j][2], o[j][3],
                            ph[t1s][0], ph[t1s][1], ph[t1s][2], ph[t1s][3], vh2, vh3);
                    MMA_F16(o[j][0], o[j][1], o[j][2], o[j][3],
                            ph[t0s][0], ph[t0s][1], ph[t0s][2], ph[t0s][3], vl0, vl1);
                    MMA_F16(o[j][0], o[j][1], o[j][2], o[j][3],
                            ph[t1s][0], ph[t1s][1], ph[t1s][2], ph[t1s][3], vl2, vl3);
                }
            }
        }
        __syncthreads();
    }

    // --- normalize + store ---
    {
        float inv0 = 1.0f / l0, inv1 = 1.0f / l1;
        float* op = g_o + ((size_t)bh * TT + q0 + wrow) * DD;
#pragma unroll
        for (int j = 0; j < 8; j++) {
            int col = j * 8 + tg * 2;
            *reinterpret_cast<float2*>(op + (size_t)g * DD + col) =
                make_float2(o[j][0] * inv0, o[j][1] * inv0);
            *reinterpret_cast<float2*>(op + (size_t)(g + 8) * DD + col) =
                make_float2(o[j][2] * inv1, o[j][3] * inv1);
        }
    }
}

// ---------------------------------------------------------------------------
// Kernel 3: output projection. grid (TT/64, BB) = 128 CTAs, 256 threads.
// out tile 64x64, micro-tile 2x8.
// ---------------------------------------------------------------------------
__global__ void __launch_bounds__(256) proj_kernel(
        const float* __restrict__ W_proj, const float* __restrict__ b_proj,
        float* __restrict__ out) {
    __shared__ __align__(16) float a_s[64][65];
    __shared__ __align__(16) float w_s[64][64];

    const int b  = blockIdx.y;
    const int t0 = blockIdx.x * 64;
    const int tid  = threadIdx.x;
    const int colg = tid & 7;
    const int rowg = tid >> 3;       // 0..31
    const int c0   = colg * 8;

    float acc[2][8] = {};
    for (int h = 0; h < HH; h++) {
        __syncthreads();
        const float* aptr = g_o + (((size_t)b * HH + h) * TT + t0) * DD;
        const float* wptr = W_proj + (size_t)h * DD * CC;
        for (int i = tid; i < 1024; i += 256) {
            int r = i >> 4, c4 = (i & 15) << 2;
            float4 v = reinterpret_cast<const float4*>(aptr)[i];
            float* dst = &a_s[r][c4];
            dst[0] = v.x; dst[1] = v.y; dst[2] = v.z; dst[3] = v.w;
            *reinterpret_cast<float4*>(&w_s[r][c4]) = reinterpret_cast<const float4*>(wptr)[i];
        }
        __syncthreads();
#pragma unroll 4
        for (int d = 0; d < DD; d++) {
            float4 w0 = *reinterpret_cast<const float4*>(&w_s[d][c0]);
            float4 w1 = *reinterpret_cast<const float4*>(&w_s[d][c0 + 4]);
#pragma unroll
            for (int i = 0; i < 2; i++) {
                float av = a_s[rowg + 32 * i][d];
                acc[i][0] = fmaf(av, w0.x, acc[i][0]);
                acc[i][1] = fmaf(av, w0.y, acc[i][1]);
                acc[i][2] = fmaf(av, w0.z, acc[i][2]);
                acc[i][3] = fmaf(av, w0.w, acc[i][3]);
                acc[i][4] = fmaf(av, w1.x, acc[i][4]);
                acc[i][5] = fmaf(av, w1.y, acc[i][5]);
                acc[i][6] = fmaf(av, w1.z, acc[i][6]);
                acc[i][7] = fmaf(av, w1.w, acc[i][7]);
            }
        }
    }

    float bp[8];
#pragma unroll
    for (int j = 0; j < 8; j++) bp[j] = b_proj[c0 + j];

    float* optr = out + ((size_t)b * TT + t0) * CC;
#pragma unroll
    for (int i = 0; i < 2; i++) {
        float4 o0 = make_float4(acc[i][0] + bp[0], acc[i][1] + bp[1],
                                acc[i][2] + bp[2], acc[i][3] + bp[3]);
        float4 o1 = make_float4(acc[i][4] + bp[4], acc[i][5] + bp[5],
                                acc[i][6] + bp[6], acc[i][7] + bp[7]);
        float* dst = optr + (size_t)(rowg + 32 * i) * CC + c0;
        *reinterpret_cast<float4*>(dst)     = o0;
        *reinterpret_cast<float4*>(dst + 4) = o1;
    }
}

// ---------------------------------------------------------------------------
extern "C" void kernel_launch(void* const* d_in, const int* in_sizes, int n_in,
                              void* d_out, int out_size) {
    const float* x      = (const float*)d_in[0];
    const float* y      = (const float*)d_in[1];
    const float* Wq     = (const float*)d_in[2];
    const float* Wk     = (const float*)d_in[3];
    const float* Wv     = (const float*)d_in[4];
    const float* W_proj = (const float*)d_in[5];
    const float* b_proj = (const float*)d_in[6];
    float* out = (float*)d_out;
    (void)in_sizes; (void)n_in; (void)out_size;

    static int inited = 0;
    if (!inited) {
        cudaFuncSetAttribute(qkv_kernel,
                             cudaFuncAttributeMaxDynamicSharedMemorySize, QKV_SMEM);
        cudaFuncSetAttribute(attn_mma_kernel,
                             cudaFuncAttributeMaxDynamicSharedMemorySize, ATTN_SMEM);
        inited = 1;
    }

    qkv_kernel<<<dim3(TT / 128, BH, 3), 128, QKV_SMEM>>>(x, y, Wq, Wk, Wv);
    attn_mma_kernel<<<(TT / 128) * BH, 256, ATTN_SMEM>>>();
    proj_kernel<<<dim3(TT / 64, BB), 256>>>(W_proj, b_proj, out);
}

// round 7
// speedup vs baseline: 3.8643x; 1.0534x over previous
#include <cuda_runtime.h>
#include <cuda_fp16.h>
#include <cstdint>

#define BB 4
#define TT 2048
#define CC 64
#define HH 6
#define DD 64
#define BH (BB*HH)
#define NEG_BIG (-1e30f)

// ---------------------------------------------------------------------------
// Scratch (__device__ globals; allocation-free rule). fp16 hi/lo splits.
// ---------------------------------------------------------------------------
__device__ __half g_xh [(size_t)BB*TT*CC];   // x split hi/lo
__device__ __half g_xl [(size_t)BB*TT*CC];
__device__ __half g_yh [(size_t)BB*TT*CC];   // y split hi/lo
__device__ __half g_yl [(size_t)BB*TT*CC];
__device__ __half g_wTh[(size_t)3*HH*CC*DD]; // W transposed [sel*H+h][d][c] hi/lo
__device__ __half g_wTl[(size_t)3*HH*CC*DD];

__device__ __half g_qh [(size_t)BH*TT*DD];   // q (pre-scaled by 0.125, hi only)
__device__ __half g_kh [(size_t)BH*TT*DD];
__device__ __half g_kl [(size_t)BH*TT*DD];
__device__ __half g_vth[(size_t)BH*DD*TT];   // v transposed: [bh][d][t]
__device__ __half g_vtl[(size_t)BH*DD*TT];
__device__ float  g_o  [(size_t)BH*TT*DD];

__device__ __forceinline__ uint32_t smem_u32(const void* p) {
    uint32_t a;
    asm("{ .reg .u64 t; cvta.to.shared.u64 t, %1; cvt.u32.u64 %0, t; }"
        : "=r"(a) : "l"(p));
    return a;
}

#define LDMATRIX_X4(r0, r1, r2, r3, addr) \
    asm volatile("ldmatrix.sync.aligned.m8n8.x4.shared.b16 {%0,%1,%2,%3}, [%4];" \
        : "=r"(r0), "=r"(r1), "=r"(r2), "=r"(r3) : "r"(addr))

#define MMA_F16(d0, d1, d2, d3, a0, a1, a2, a3, b0, b1) \
    asm volatile("mma.sync.aligned.m16n8k16.row.col.f32.f16.f16.f32 " \
        "{%0,%1,%2,%3}, {%4,%5,%6,%7}, {%8,%9}, {%0,%1,%2,%3};" \
        : "+f"(d0), "+f"(d1), "+f"(d2), "+f"(d3) \
        : "r"(a0), "r"(a1), "r"(a2), "r"(a3), "r"(b0), "r"(b1))

#define CP_ASYNC16(saddr, gaddr) \
    asm volatile("cp.async.cg.shared.global [%0], [%1], 16;" \
        :: "r"(saddr), "l"(gaddr) : "memory")
#define CP_COMMIT() asm volatile("cp.async.commit_group;" ::: "memory")
#define CP_WAIT0()  asm volatile("cp.async.wait_group 0;" ::: "memory")

__device__ __forceinline__ uint32_t pack_h2(__half a, __half b) {
    return (uint32_t)__half_as_ushort(a) | ((uint32_t)__half_as_ushort(b) << 16);
}
__device__ __forceinline__ void split_h(float v, __half& hi, __half& lo) {
    hi = __float2half_rn(v);
    lo = __float2half_rn(v - __half2float(hi));
}

// ---------------------------------------------------------------------------
// Prep 1: split x,y fp32 -> fp16 hi/lo. 131072 float4 per tensor.
// ---------------------------------------------------------------------------
__global__ void __launch_bounds__(256) prep_xy(const float* __restrict__ x,
                                               const float* __restrict__ y) {
    const int n4 = BB * TT * CC / 4;   // 131072
    for (int i = blockIdx.x * 256 + threadIdx.x; i < 2 * n4; i += gridDim.x * 256) {
        bool isx = (i < n4);
        int j = isx ? i : i - n4;
        float4 v = reinterpret_cast<const float4*>(isx ? x : y)[j];
        __half h0, h1, h2, h3, l0, l1, l2, l3;
        split_h(v.x, h0, l0); split_h(v.y, h1, l1);
        split_h(v.z, h2, l2); split_h(v.w, h3, l3);
        uint2 hv = make_uint2(pack_h2(h0, h1), pack_h2(h2, h3));
        uint2 lv = make_uint2(pack_h2(l0, l1), pack_h2(l2, l3));
        *reinterpret_cast<uint2*>((isx ? g_xh : g_yh) + (size_t)j * 4) = hv;
        *reinterpret_cast<uint2*>((isx ? g_xl : g_yl) + (size_t)j * 4) = lv;
    }
}

// ---------------------------------------------------------------------------
// Prep 2: transpose + split weights. grid 3*H CTAs, 128 threads.
// out[sh][d][c] = W_sh[c][d]
// ---------------------------------------------------------------------------
__global__ void __launch_bounds__(128) prep_w(const float* __restrict__ Wq,
                                              const float* __restrict__ Wk,
                                              const float* __restrict__ Wv) {
    const int sh = blockIdx.x;            // 0..17
    const int sel = sh / HH, h = sh % HH;
    const float* W = (sel == 0 ? Wq : (sel == 1 ? Wk : Wv)) + (size_t)h * CC * DD;
    __half* oh = g_wTh + (size_t)sh * CC * DD;
    __half* ol = g_wTl + (size_t)sh * CC * DD;
    for (int i = threadIdx.x; i < CC * DD; i += 128) {
        int d = i >> 6, c = i & 63;
        float v = W[c * DD + d];
        __half hh, ll;
        split_h(v, hh, ll);
        oh[i] = hh;
        ol[i] = ll;
    }
}

// ---------------------------------------------------------------------------
// Kernel 1: QKV projection via mma.sync (fp16 hi/lo, 3 chains), cp.async in.
// grid (TT/128, BH, 3), block 128 (4 warps x 32 rows).
// ---------------------------------------------------------------------------
#define XS 72
#define QKV_SMEM ((2*128*XS + 2*64*XS) * 2)

__global__ void __launch_bounds__(128) qkv_kernel() {
    extern __shared__ __align__(16) __half qsm[];
    __half* xh  = qsm;
    __half* xl  = xh + 128 * XS;
    __half* wTh = xl + 128 * XS;
    __half* wTl = wTh + 64 * XS;

    const int sel = blockIdx.z;
    const int bh  = blockIdx.y;
    const int b   = bh / HH, h = bh % HH;
    const int t0  = blockIdx.x * 128;

    const __half* srcH = (sel == 0 ? g_xh : g_yh) + ((size_t)b * TT + t0) * CC;
    const __half* srcL = (sel == 0 ? g_xl : g_yl) + ((size_t)b * TT + t0) * CC;
    const __half* wH   = g_wTh + (size_t)(sel * HH + h) * CC * DD;
    const __half* wL   = g_wTl + (size_t)(sel * HH + h) * CC * DD;

    const int tid  = threadIdx.x;
    const int wid  = tid >> 5, lane = tid & 31;
    const int g    = lane >> 2, tg = lane & 3;
    const int wrow = wid * 32;
    const int lrow = lane & 7;
    const int l8   = (lane >> 3) & 1;
    const int l16  = lane >> 4;

    const uint32_t xh_b  = smem_u32(xh);
    const uint32_t xl_b  = smem_u32(xl);
    const uint32_t wTh_b = smem_u32(wTh);
    const uint32_t wTl_b = smem_u32(wTl);

    // stage everything via cp.async (no conversion)
#pragma unroll
    for (int u = tid; u < 1024; u += 128) {        // x: 128 rows x 8 chunks
        int r = u >> 3, ch = (u & 7) * 8;
        uint32_t off = (uint32_t)(r * XS + ch) * 2;
        CP_ASYNC16(xh_b + off, srcH + (size_t)r * CC + ch);
        CP_ASYNC16(xl_b + off, srcL + (size_t)r * CC + ch);
    }
#pragma unroll
    for (int u = tid; u < 512; u += 128) {         // w: 64 rows x 8 chunks
        int r = u >> 3, ch = (u & 7) * 8;
        uint32_t off = (uint32_t)(r * XS + ch) * 2;
        CP_ASYNC16(wTh_b + off, wH + (size_t)r * CC + ch);
        CP_ASYNC16(wTl_b + off, wL + (size_t)r * CC + ch);
    }
    CP_COMMIT();
    CP_WAIT0();
    __syncthreads();

    float acc[2][8][4] = {};

#pragma unroll
    for (int kw = 0; kw < 2; kw++) {          // two k32 windows
        const int ck = kw * 32;
        uint32_t ah[2][2][4], al[2][2][4];    // [m][k16][reg]
#pragma unroll
        for (int m = 0; m < 2; m++)
#pragma unroll
            for (int kk = 0; kk < 2; kk++) {
                uint32_t off = (uint32_t)((wrow + m * 16 + lrow + l8 * 8) * XS
                                          + ck + kk * 16 + l16 * 8) * 2;
                LDMATRIX_X4(ah[m][kk][0], ah[m][kk][1], ah[m][kk][2], ah[m][kk][3],
                            xh_b + off);
                LDMATRIX_X4(al[m][kk][0], al[m][kk][1], al[m][kk][2], al[m][kk][3],
                            xl_b + off);
            }
#pragma unroll
        for (int j = 0; j < 8; j++) {
            uint32_t boff = (uint32_t)((j * 8 + lrow) * XS + ck + (lane >> 3) * 8) * 2;
            uint32_t bh0, bh1, bh2, bh3, bl0, bl1, bl2, bl3;
            LDMATRIX_X4(bh0, bh1, bh2, bh3, wTh_b + boff);
            LDMATRIX_X4(bl0, bl1, bl2, bl3, wTl_b + boff);
#pragma unroll
            for (int m = 0; m < 2; m++) {
                MMA_F16(acc[m][j][0], acc[m][j][1], acc[m][j][2], acc[m][j][3],
                        ah[m][0][0], ah[m][0][1], ah[m][0][2], ah[m][0][3], bh0, bh1);
                MMA_F16(acc[m][j][0], acc[m][j][1], acc[m][j][2], acc[m][j][3],
                        ah[m][1][0], ah[m][1][1], ah[m][1][2], ah[m][1][3], bh2, bh3);
                MMA_F16(acc[m][j][0], acc[m][j][1], acc[m][j][2], acc[m][j][3],
                        ah[m][0][0], ah[m][0][1], ah[m][0][2], ah[m][0][3], bl0, bl1);
                MMA_F16(acc[m][j][0], acc[m][j][1], acc[m][j][2], acc[m][j][3],
                        ah[m][1][0], ah[m][1][1], ah[m][1][2], ah[m][1][3], bl2, bl3);
                MMA_F16(acc[m][j][0], acc[m][j][1], acc[m][j][2], acc[m][j][3],
                        al[m][0][0], al[m][0][1], al[m][0][2], al[m][0][3], bh0, bh1);
                MMA_F16(acc[m][j][0], acc[m][j][1], acc[m][j][2], acc[m][j][3],
                        al[m][1][0], al[m][1][1], al[m][1][2], al[m][1][3], bh2, bh3);
            }
        }
    }

    if (sel == 0) {
        // Q: pre-scale by 0.125 (softmax scale folded), store hi only
#pragma unroll
        for (int m = 0; m < 2; m++)
#pragma unroll
            for (int j = 0; j < 8; j++) {
                int r0 = t0 + wrow + m * 16 + g;
                int col = j * 8 + tg * 2;
                *reinterpret_cast<uint32_t*>(g_qh + ((size_t)bh * TT + r0) * DD + col) =
                    pack_h2(__float2half_rn(acc[m][j][0] * 0.125f),
                            __float2half_rn(acc[m][j][1] * 0.125f));
                *reinterpret_cast<uint32_t*>(g_qh + ((size_t)bh * TT + r0 + 8) * DD + col) =
                    pack_h2(__float2half_rn(acc[m][j][2] * 0.125f),
                            __float2half_rn(acc[m][j][3] * 0.125f));
            }
    } else if (sel == 1) {
        // K: store hi + lo
#pragma unroll
        for (int m = 0; m < 2; m++)
#pragma unroll
            for (int j = 0; j < 8; j++) {
                int r0 = t0 + wrow + m * 16 + g;
                int col = j * 8 + tg * 2;
                __half h0, h1, h2, h3, l0, l1, l2, l3;
                split_h(acc[m][j][0], h0, l0); split_h(acc[m][j][1], h1, l1);
                split_h(acc[m][j][2], h2, l2); split_h(acc[m][j][3], h3, l3);
                size_t ba = ((size_t)bh * TT + r0) * DD + col;
                size_t bb = ((size_t)bh * TT + r0 + 8) * DD + col;
                *reinterpret_cast<uint32_t*>(g_kh + ba) = pack_h2(h0, h1);
                *reinterpret_cast<uint32_t*>(g_kh + bb) = pack_h2(h2, h3);
                *reinterpret_cast<uint32_t*>(g_kl + ba) = pack_h2(l0, l1);
                *reinterpret_cast<uint32_t*>(g_kl + bb) = pack_h2(l2, l3);
            }
    } else {
        // V: transpose via smem staging (reuse xh/xl as [64 d][136 t])
        __syncthreads();
        __half* vsh = xh;
        __half* vsl = xl;
#pragma unroll
        for (int m = 0; m < 2; m++)
#pragma unroll
            for (int j = 0; j < 8; j++) {
                int tA  = wrow + m * 16 + g;
                int tBr = tA + 8;
                int d0  = j * 8 + tg * 2;
                __half hh, ll;
                split_h(acc[m][j][0], hh, ll);
                vsh[(d0)     * 136 + tA]  = hh; vsl[(d0)     * 136 + tA]  = ll;
                split_h(acc[m][j][1], hh, ll);
                vsh[(d0 + 1) * 136 + tA]  = hh; vsl[(d0 + 1) * 136 + tA]  = ll;
                split_h(acc[m][j][2], hh, ll);
                vsh[(d0)     * 136 + tBr] = hh; vsl[(d0)     * 136 + tBr] = ll;
                split_h(acc[m][j][3], hh, ll);
                vsh[(d0 + 1) * 136 + tBr] = hh; vsl[(d0 + 1) * 136 + tBr] = ll;
            }
        __syncthreads();
        for (int u = tid; u < 1024; u += 128) {
            int d = u >> 4, tc = (u & 15) * 8;
            uint4 hv = *reinterpret_cast<uint4*>(vsh + d * 136 + tc);
            uint4 lv = *reinterpret_cast<uint4*>(vsl + d * 136 + tc);
            size_t dst = ((size_t)bh * DD + d) * TT + t0 + tc;
            *reinterpret_cast<uint4*>(g_vth + dst) = hv;
            *reinterpret_cast<uint4*>(g_vtl + dst) = lv;
        }
    }
}

// ---------------------------------------------------------------------------
// Kernel 2: causal flash attention via mma.sync (fp16, 2 chains).
// 128 q-rows per CTA, 8 warps, key tiles of 64, cp.async double buffer,
// ONE __syncthreads per tile.
// ---------------------------------------------------------------------------
#define KSTRIDE 72                      // fp16 elems per smem row (144 B)
#define ARR_B   (64 * KSTRIDE * 2)      // 9216 B per array
#define STG_B   (4 * ARR_B)             // 36864 B per stage
#define ATTN_SMEM (2 * STG_B)           // 73728 B

__global__ void __launch_bounds__(256) attn_mma_kernel() {
    extern __shared__ __align__(16) char smem[];
    const uint32_t sbase = smem_u32(smem);

    const int tid  = threadIdx.x;
    const int wid  = tid >> 5, lane = tid & 31;
    const int g    = lane >> 2, tg = lane & 3;
    const int bid  = blockIdx.x;
    const int qt   = (TT / 128 - 1) - bid / BH;    // heavy tiles first
    const int bh   = bid % BH;
    const int q0   = qt * 128;
    const int wrow = wid * 16;
    const int njt  = 2 * qt + 2;

    const __half* khB = g_kh + (size_t)bh * TT * DD;
    const __half* klB = g_kl + (size_t)bh * TT * DD;
    const __half* vhB = g_vth + (size_t)bh * DD * TT;
    const __half* vlB = g_vtl + (size_t)bh * DD * TT;

    auto stage = [&](int jt) {
        const int j0 = jt * 64;
        const uint32_t so = sbase + (uint32_t)(jt & 1) * STG_B;
#pragma unroll
        for (int u = tid; u < 512; u += 256) {
            int r = u >> 3, ch = (u & 7) * 8;
            uint32_t off = (uint32_t)(r * (KSTRIDE * 2) + ch * 2);
            CP_ASYNC16(so + off,              khB + (size_t)(j0 + r) * DD + ch);
            CP_ASYNC16(so + ARR_B + off,      klB + (size_t)(j0 + r) * DD + ch);
            CP_ASYNC16(so + 2 * ARR_B + off,  vhB + (size_t)r * TT + j0 + ch);
            CP_ASYNC16(so + 3 * ARR_B + off,  vlB + (size_t)r * TT + j0 + ch);
        }
        CP_COMMIT();
    };

    // --- Q fragments (hi only, pre-scaled, loaded once) ---
    uint32_t qh[4][4];
    {
        const __half* qb = g_qh + ((size_t)bh * TT + q0 + wrow) * DD;
#pragma unroll
        for (int t = 0; t < 4; t++) {
            int col0 = t * 16 + tg * 2;
            qh[t][0] = *reinterpret_cast<const uint32_t*>(qb + (size_t)g * DD + col0);
            qh[t][1] = *reinterpret_cast<const uint32_t*>(qb + (size_t)(g + 8) * DD + col0);
            qh[t][2] = *reinterpret_cast<const uint32_t*>(qb + (size_t)g * DD + col0 + 8);
            qh[t][3] = *reinterpret_cast<const uint32_t*>(qb + (size_t)(g + 8) * DD + col0 + 8);
        }
    }

    float o[8][4];
#pragma unroll
    for (int j = 0; j < 8; j++)
#pragma unroll
        for (int e = 0; e < 4; e++) o[j][e] = 0.0f;
    float m0 = NEG_BIG, m1 = NEG_BIG, l0 = 0.0f, l1 = 0.0f;
    const int row0 = q0 + wrow + g, row1 = row0 + 8;
    const int rowmax = q0 + wrow + 15;

    const int lrow = lane & 7;
    const int lmi  = lane >> 3;

    stage(0);

    for (int jt = 0; jt < njt; jt++) {
        const int j0 = jt * 64;
        CP_WAIT0();
        __syncthreads();                 // all warps done with buffer (jt-1)&1
        if (jt + 1 < njt) stage(jt + 1); // writes buffer (jt+1)&1 — safe

        if (j0 <= rowmax) {
            const uint32_t so = sbase + (uint32_t)(jt & 1) * STG_B;
            const uint32_t skh_b = so;
            const uint32_t skl_b = so + ARR_B;
            const uint32_t svh_b = so + 2 * ARR_B;
            const uint32_t svl_b = so + 3 * ARR_B;

            // --- S = Q K^T (2 chains: qh*kh + qh*kl), pre-scaled ---
            float c[8][4];
#pragma unroll
            for (int j = 0; j < 8; j++)
#pragma unroll
                for (int e = 0; e < 4; e++) c[j][e] = 0.0f;

#pragma unroll
            for (int j = 0; j < 8; j++) {
                uint32_t roff = (uint32_t)((j * 8 + lrow) * KSTRIDE + lmi * 8) * 2;
#pragma unroll
                for (int tp = 0; tp < 2; tp++) {
                    uint32_t coff = roff + (uint32_t)(tp * 64);
                    uint32_t kh0, kh1, kh2, kh3, kl0, kl1, kl2, kl3;
                    LDMATRIX_X4(kh0, kh1, kh2, kh3, skh_b + coff);
                    LDMATRIX_X4(kl0, kl1, kl2, kl3, skl_b + coff);
                    int t0s = 2 * tp, t1s = 2 * tp + 1;
                    MMA_F16(c[j][0], c[j][1], c[j][2], c[j][3],
                            qh[t0s][0], qh[t0s][1], qh[t0s][2], qh[t0s][3], kh0, kh1);
                    MMA_F16(c[j][0], c[j][1], c[j][2], c[j][3],
                            qh[t1s][0], qh[t1s][1], qh[t1s][2], qh[t1s][3], kh2, kh3);
                    MMA_F16(c[j][0], c[j][1], c[j][2], c[j][3],
                            qh[t0s][0], qh[t0s][1], qh[t0s][2], qh[t0s][3], kl0, kl1);
                    MMA_F16(c[j][0], c[j][1], c[j][2], c[j][3],
                            qh[t1s][0], qh[t1s][1], qh[t1s][2], qh[t1s][3], kl2, kl3);
                }
            }

            // --- softmax (S already scaled) ---
            const bool m0p = (j0 + 63 > row0);
            const bool m1p = (j0 + 63 > row1);
            float mx0 = NEG_BIG, mx1 = NEG_BIG;
#pragma unroll
            for (int j = 0; j < 8; j++) {
#pragma unroll
                for (int e = 0; e < 2; e++) {
                    int col = j0 + j * 8 + tg * 2 + e;
                    float v0 = c[j][e];
                    float v1 = c[j][2 + e];
                    if (m0p && col > row0) v0 = NEG_BIG;
                    if (m1p && col > row1) v1 = NEG_BIG;
                    c[j][e] = v0; c[j][2 + e] = v1;
                    mx0 = fmaxf(mx0, v0); mx1 = fmaxf(mx1, v1);
                }
            }
            mx0 = fmaxf(mx0, __shfl_xor_sync(0xffffffffu, mx0, 1));
            mx0 = fmaxf(mx0, __shfl_xor_sync(0xffffffffu, mx0, 2));
            mx1 = fmaxf(mx1, __shfl_xor_sync(0xffffffffu, mx1, 1));
            mx1 = fmaxf(mx1, __shfl_xor_sync(0xffffffffu, mx1, 2));

            float mn0 = fmaxf(m0, mx0), mn1 = fmaxf(m1, mx1);
            float corr0 = __expf(m0 - mn0), corr1 = __expf(m1 - mn1);
            m0 = mn0; m1 = mn1;

            float s0 = 0.0f, s1 = 0.0f;
#pragma unroll
            for (int j = 0; j < 8; j++) {
#pragma unroll
                for (int e = 0; e < 2; e++) {
                    float p0 = __expf(c[j][e] - mn0);
                    float p1 = __expf(c[j][2 + e] - mn1);
                    c[j][e] = p0; c[j][2 + e] = p1;
                    s0 += p0; s1 += p1;
                }
            }
            s0 += __shfl_xor_sync(0xffffffffu, s0, 1);
            s0 += __shfl_xor_sync(0xffffffffu, s0, 2);
            s1 += __shfl_xor_sync(0xffffffffu, s1, 1);
            s1 += __shfl_xor_sync(0xffffffffu, s1, 2);
            l0 = l0 * corr0 + s0;
            l1 = l1 * corr1 + s1;

#pragma unroll
            for (int j = 0; j < 8; j++) {
                o[j][0] *= corr0; o[j][1] *= corr0;
                o[j][2] *= corr1; o[j][3] *= corr1;
            }

            // --- P fragments (hi only) ---
            uint32_t ph[4][4];
#pragma unroll
            for (int t = 0; t < 4; t++) {
                ph[t][0] = pack_h2(__float2half_rn(c[2*t][0]),   __float2half_rn(c[2*t][1]));
                ph[t][1] = pack_h2(__float2half_rn(c[2*t][2]),   __float2half_rn(c[2*t][3]));
                ph[t][2] = pack_h2(__float2half_rn(c[2*t+1][0]), __float2half_rn(c[2*t+1][1]));
                ph[t][3] = pack_h2(__float2half_rn(c[2*t+1][2]), __float2half_rn(c[2*t+1][3]));
            }

            // --- O += P V (2 chains: ph*vh + ph*vl) ---
#pragma unroll
            for (int j = 0; j < 8; j++) {
                uint32_t roff = (uint32_t)((j * 8 + lrow) * KSTRIDE + lmi * 8) * 2;
#pragma unroll
                for (int tp = 0; tp < 2; tp++) {
                    uint32_t coff = roff + (uint32_t)(tp * 64);
                    uint32_t vh0, vh1, vh2, vh3, vl0, vl1, vl2, vl3;
                    LDMATRIX_X4(vh0, vh1, vh2, vh3, svh_b + coff);
                    LDMATRIX_X4(vl0, vl1, vl2, vl3, svl_b + coff);
                    int t0s = 2 * tp, t1s = 2 * tp + 1;
                    MMA_F16(o[j][0], o[j][1], o[j][2], o[j][3],
                            ph[t0s][0], ph[t0s][1], ph[t0s][2], ph[t0s][3], vh0, vh1);
                    MMA_F16(o[j][0], o[j][1], o[j][2], o[j][3],
                            ph[t1s][0], ph[t1s][1], ph[t1s][2], ph[t1s][3], vh2, vh3);
                    MMA_F16(o[j][0], o[j][1], o[j][2], o[j][3],
                            ph[t0s][0], ph[t0s][1], ph[t0s][2], ph[t0s][3], vl0, vl1);
                    MMA_F16(o[j][0], o[j][1], o[j][2], o[j][3],
                            ph[t1s][0], ph[t1s][1], ph[t1s][2], ph[t1s][3], vl2, vl3);
                }
            }
        }
    }

    // --- normalize + store ---
    {
        float inv0 = 1.0f / l0, inv1 = 1.0f / l1;
        float* op = g_o + ((size_t)bh * TT + q0 + wrow) * DD;
#pragma unroll
        for (int j = 0; j < 8; j++) {
            int col = j * 8 + tg * 2;
            *reinterpret_cast<float2*>(op + (size_t)g * DD + col) =
                make_float2(o[j][0] * inv0, o[j][1] * inv0);
            *reinterpret_cast<float2*>(op + (size_t)(g + 8) * DD + col) =
                make_float2(o[j][2] * inv1, o[j][3] * inv1);
        }
    }
}

// ---------------------------------------------------------------------------
// Kernel 3: output projection. grid (TT/64, BB) = 128 CTAs, 256 threads.
// ---------------------------------------------------------------------------
__global__ void __launch_bounds__(256) proj_kernel(
        const float* __restrict__ W_proj, const float* __restrict__ b_proj,
        float* __restrict__ out) {
    __shared__ __align__(16) float a_s[64][65];
    __shared__ __align__(16) float w_s[64][64];

    const int b  = blockIdx.y;
    const int t0 = blockIdx.x * 64;
    const int tid  = threadIdx.x;
    const int colg = tid & 7;
    const int rowg = tid >> 3;       // 0..31
    const int c0   = colg * 8;

    float acc[2][8] = {};
    for (int h = 0; h < HH; h++) {
        __syncthreads();
        const float* aptr = g_o + (((size_t)b * HH + h) * TT + t0) * DD;
        const float* wptr = W_proj + (size_t)h * DD * CC;
        for (int i = tid; i < 1024; i += 256) {
            int r = i >> 4, c4 = (i & 15) << 2;
            float4 v = reinterpret_cast<const float4*>(aptr)[i];
            float* dst = &a_s[r][c4];
            dst[0] = v.x; dst[1] = v.y; dst[2] = v.z; dst[3] = v.w;
            *reinterpret_cast<float4*>(&w_s[r][c4]) = reinterpret_cast<const float4*>(wptr)[i];
        }
        __syncthreads();
#pragma unroll 4
        for (int d = 0; d < DD; d++) {
            float4 w0 = *reinterpret_cast<const float4*>(&w_s[d][c0]);
            float4 w1 = *reinterpret_cast<const float4*>(&w_s[d][c0 + 4]);
#pragma unroll
            for (int i = 0; i < 2; i++) {
                float av = a_s[rowg + 32 * i][d];
                acc[i][0] = fmaf(av, w0.x, acc[i][0]);
                acc[i][1] = fmaf(av, w0.y, acc[i][1]);
                acc[i][2] = fmaf(av, w0.z, acc[i][2]);
                acc[i][3] = fmaf(av, w0.w, acc[i][3]);
                acc[i][4] = fmaf(av, w1.x, acc[i][4]);
                acc[i][5] = fmaf(av, w1.y, acc[i][5]);
                acc[i][6] = fmaf(av, w1.z, acc[i][6]);
                acc[i][7] = fmaf(av, w1.w, acc[i][7]);
            }
        }
    }

    float bp[8];
#pragma unroll
    for (int j = 0; j < 8; j++) bp[j] = b_proj[c0 + j];

    float* optr = out + ((size_t)b * TT + t0) * CC;
#pragma unroll
    for (int i = 0; i < 2; i++) {
        float4 o0 = make_float4(acc[i][0] + bp[0], acc[i][1] + bp[1],
                                acc[i][2] + bp[2], acc[i][3] + bp[3]);
        float4 o1 = make_float4(acc[i][4] + bp[4], acc[i][5] + bp[5],
                                acc[i][6] + bp[6], acc[i][7] + bp[7]);
        float* dst = optr + (size_t)(rowg + 32 * i) * CC + c0;
        *reinterpret_cast<float4*>(dst)     = o0;
        *reinterpret_cast<float4*>(dst + 4) = o1;
    }
}

// ---------------------------------------------------------------------------
extern "C" void kernel_launch(void* const* d_in, const int* in_sizes, int n_in,
                              void* d_out, int out_size) {
    const float* x      = (const float*)d_in[0];
    const float* y      = (const float*)d_in[1];
    const float* Wq     = (const float*)d_in[2];
    const float* Wk     = (const float*)d_in[3];
    const float* Wv     = (const float*)d_in[4];
    const float* W_proj = (const float*)d_in[5];
    const float* b_proj = (const float*)d_in[6];
    float* out = (float*)d_out;
    (void)in_sizes; (void)n_in; (void)out_size;

    static int inited = 0;
    if (!inited) {
        cudaFuncSetAttribute(qkv_kernel,
                             cudaFuncAttributeMaxDynamicSharedMemorySize, QKV_SMEM);
        cudaFuncSetAttribute(attn_mma_kernel,
                             cudaFuncAttributeMaxDynamicSharedMemorySize, ATTN_SMEM);
        inited = 1;
    }

    prep_xy<<<256, 256>>>(x, y);
    prep_w<<<3 * HH, 128>>>(Wq, Wk, Wv);
    qkv_kernel<<<dim3(TT / 128, BH, 3), 128, QKV_SMEM>>>();
    attn_mma_kernel<<<(TT / 128) * BH, 256, ATTN_SMEM>>>();
    proj_kernel<<<dim3(TT / 64, BB), 256>>>(W_proj, b_proj, out);
}